// round 8
// baseline (speedup 1.0000x reference)
#include <cuda_runtime.h>
#include <cuda_fp16.h>
#include <math.h>
#include <stdint.h>

// ---------------- problem constants ----------------
#define N_TOK 32768
#define HDIM  1152
#define LIGHT 1152
#define HEAVY 4608

// ---------------- static scratch (fp16 operands) ----------------
__device__ __half g_hl [(size_t)N_TOK * LIGHT];   // p0 * gelu(fc1_light)
__device__ __half g_hh [(size_t)N_TOK * HEAVY];   // p1 * gelu(fc1_heavy)
__device__ __half g_xh [(size_t)N_TOK * HDIM];
__device__ __half g_lw1h[(size_t)LIGHT * HDIM];
__device__ __half g_hw1h[(size_t)HEAVY * HDIM];
__device__ __half g_lw2h[(size_t)HDIM * LIGHT];
__device__ __half g_hw2h[(size_t)HDIM * HEAVY];
__device__ float  g_probs[2 * N_TOK];

__device__ __forceinline__ uint32_t smem_u32(const void* p) {
    uint32_t a;
    asm("{ .reg .u64 t; cvta.to.shared.u64 t, %1; cvt.u32.u64 %0, t; }" : "=r"(a) : "l"(p));
    return a;
}
__device__ __forceinline__ void cp_async16(uint32_t s, const void* g) {
    size_t gp = __cvta_generic_to_global(g);
    asm volatile("cp.async.cg.shared.global [%0], [%1], 16;" :: "r"(s), "l"(gp) : "memory");
}
#define CP_COMMIT() asm volatile("cp.async.commit_group;" ::: "memory")
#define CP_WAIT2()  asm volatile("cp.async.wait_group 2;" ::: "memory")
#define CP_WAIT0()  asm volatile("cp.async.wait_group 0;" ::: "memory")

__device__ __forceinline__ void ldmatrix_x4(uint32_t& r0, uint32_t& r1,
                                            uint32_t& r2, uint32_t& r3, uint32_t addr) {
    asm volatile("ldmatrix.sync.aligned.m8n8.x4.shared.b16 {%0,%1,%2,%3}, [%4];"
                 : "=r"(r0), "=r"(r1), "=r"(r2), "=r"(r3) : "r"(addr));
}
__device__ __forceinline__ void mma_f16(float* d, const uint32_t* a, const uint32_t* b) {
    asm volatile(
        "mma.sync.aligned.m16n8k16.row.col.f32.f16.f16.f32 "
        "{%0,%1,%2,%3}, {%4,%5,%6,%7}, {%8,%9}, {%0,%1,%2,%3};"
        : "+f"(d[0]), "+f"(d[1]), "+f"(d[2]), "+f"(d[3])
        : "r"(a[0]), "r"(a[1]), "r"(a[2]), "r"(a[3]), "r"(b[0]), "r"(b[1]));
}

__device__ __forceinline__ float gelu_exact(float v) {
    return 0.5f * v * (1.0f + erff(v * 0.70710678118654752f));
}

// -------------------- fp32 -> fp16 weight pre-round --------------------
__global__ void round16_kernel(const float* __restrict__ in, __half* __restrict__ outp, int n4) {
    int i = blockIdx.x * blockDim.x + threadIdx.x;
    if (i < n4) {
        float4 v = ((const float4*)in)[i];
        ((__half2*)outp)[2 * i]     = __floats2half2_rn(v.x, v.y);
        ((__half2*)outp)[2 * i + 1] = __floats2half2_rn(v.z, v.w);
    }
}

// -------------------- router (also converts x -> fp16) --------------------
__global__ void router_kernel(const float* __restrict__ x,
                              const float* __restrict__ rw,
                              const float* __restrict__ rb,
                              float* __restrict__ probs,
                              __half* __restrict__ xh) {
    int warp = (blockIdx.x * blockDim.x + threadIdx.x) >> 5;
    int lane = threadIdx.x & 31;
    if (warp >= N_TOK) return;
    const float* xp = x + (size_t)warp * HDIM;
    __half* xo = xh + (size_t)warp * HDIM;
    float a0 = 0.f, a1 = 0.f;
    #pragma unroll 4
    for (int h = lane; h < HDIM; h += 32) {
        float v = xp[h];
        xo[h] = __float2half_rn(v);
        a0 = fmaf(v, rw[h], a0);
        a1 = fmaf(v, rw[HDIM + h], a1);
    }
    #pragma unroll
    for (int off = 16; off; off >>= 1) {
        a0 += __shfl_xor_sync(0xffffffffu, a0, off);
        a1 += __shfl_xor_sync(0xffffffffu, a1, off);
    }
    if (lane == 0) {
        a0 += rb[0];
        a1 += rb[1];
        float m = fmaxf(a0, a1);
        float e0 = __expf(a0 - m), e1 = __expf(a1 - m);
        float inv = 1.0f / (e0 + e1);
        probs[2 * warp]     = e0 * inv;
        probs[2 * warp + 1] = e1 * inv;
    }
}

// -------------------- fp16 mma GEMM --------------------
// CTA 256x128, 256 threads, 8 warps (4 row-groups x 2 col-groups), warp 64x64.
// BK=64, 4-stage cp.async, 192KB smem (1 CTA/SM).
// Smem row = 64 halves = 128B; 16B-unit s stored at s ^ (row & 7).
// Stage layout: [A 256x128B = 32KB][W 128x128B = 16KB], stride 48KB.
// MODE 0 (fc1): C[fp16] = probs[n,expert] * gelu(acc + b0[m]);  single segment.
// MODE 1 (fc2): C[fp32] = acc(seg0) + acc(seg1) + p0*b0[m] + p1*b1[m]; dual segment.
#define STAGE_B 49152u
#define SMEM_BYTES (4 * 49152)

template <int MODE, typename OutT>
__global__ void __launch_bounds__(256, 1) gemm_f16_kernel(
    const __half* __restrict__ A0, const __half* __restrict__ W0, int K0,
    const __half* __restrict__ A1, const __half* __restrict__ W1, int K1,
    const float* __restrict__ b0v, const float* __restrict__ b1v,
    OutT* __restrict__ C, const float* __restrict__ probs, int expert, int Nfeat)
{
    extern __shared__ char smc[];
    const uint32_t sbase = smem_u32(smc);
    const int tid  = threadIdx.x;
    const int wid  = tid >> 5, lane = tid & 31;
    const int wr   = wid >> 1;      // 0..3 : 64-row group
    const int wn   = wid & 1;       // 0..1 : 64-col group
    const int g    = lane >> 2;     // 0..7
    const int c    = lane & 3;      // 0..3
    const int row0 = blockIdx.y * 256;
    const int col0 = blockIdx.x * 128;

    // ---- cp.async mapping: lrow = tid>>3 (0..31), ls = tid&7
    const int lrow = tid >> 3;
    const int ls   = tid & 7;
    const uint32_t offR = (uint32_t)(lrow * 128 + ((ls ^ (lrow & 7)) * 16));

    // ---- ldmatrix lane components (row&7 constant across 16-row steps)
    const int arow = wr * 64 + (lane & 15);
    const int asel = lane >> 4;
    const int nrow = wn * 64 + (lane & 7) + ((lane >> 4) << 3);
    const int bsel = (lane >> 3) & 1;

    float acc[4][8][4];
    #pragma unroll
    for (int i = 0; i < 4; i++)
        #pragma unroll
        for (int j = 0; j < 8; j++)
            #pragma unroll
            for (int q = 0; q < 4; q++) acc[i][j][q] = 0.f;

    const int KT0 = K0 >> 6;
    const int KT  = KT0 + ((MODE == 1) ? (K1 >> 6) : 0);

    auto issue = [&](int kt) {
        const uint32_t so = (uint32_t)(kt & 3) * STAGE_B;
        const __half* a;
        const __half* w;
        int K;
        if (MODE == 0 || kt < KT0) {
            K = K0;
            a = A0 + (size_t)(row0 + lrow) * K0 + ls * 8 + kt * 64;
            w = W0 + (size_t)(col0 + lrow) * K0 + ls * 8 + kt * 64;
        } else {
            K = K1;
            int kl = kt - KT0;
            a = A1 + (size_t)(row0 + lrow) * K1 + ls * 8 + kl * 64;
            w = W1 + (size_t)(col0 + lrow) * K1 + ls * 8 + kl * 64;
        }
        #pragma unroll
        for (int i = 0; i < 8; i++)    // A: 256 rows
            cp_async16(sbase + so + offR + (uint32_t)i * 4096u, a + (size_t)(i * 32) * K);
        #pragma unroll
        for (int i = 0; i < 4; i++)    // W: 128 rows
            cp_async16(sbase + so + 32768u + offR + (uint32_t)i * 4096u, w + (size_t)(i * 32) * K);
    };

    auto compute = [&](int st) {
        const uint32_t as = sbase + (uint32_t)st * STAGE_B;
        const uint32_t ws = as + 32768u;
        #pragma unroll
        for (int ks = 0; ks < 4; ks++) {
            const int ua = ks * 2 + asel;
            const int ub = ks * 2 + bsel;
            uint32_t af[4][4], bf[4][4];
            #pragma unroll
            for (int i = 0; i < 4; i++) {
                int r = arow + i * 16;
                uint32_t addr = as + (uint32_t)(r * 128 + ((ua ^ (arow & 7)) * 16));
                ldmatrix_x4(af[i][0], af[i][1], af[i][2], af[i][3], addr);
            }
            #pragma unroll
            for (int j2 = 0; j2 < 4; j2++) {
                int r = nrow + j2 * 16;
                uint32_t addr = ws + (uint32_t)(r * 128 + ((ub ^ (nrow & 7)) * 16));
                ldmatrix_x4(bf[j2][0], bf[j2][1], bf[j2][2], bf[j2][3], addr);
            }
            #pragma unroll
            for (int i = 0; i < 4; i++)
                #pragma unroll
                for (int j = 0; j < 8; j++)
                    mma_f16(acc[i][j], af[i], &bf[j >> 1][(j & 1) * 2]);
        }
    };

    issue(0); CP_COMMIT();
    issue(1); CP_COMMIT();
    issue(2); CP_COMMIT();
    for (int kt = 0; kt < KT; kt++) {
        CP_WAIT2();                 // stage kt resident
        __syncthreads();            // stage (kt+3)&3 free (compute kt-1 done)
        if (kt + 3 < KT) issue(kt + 3);
        CP_COMMIT();
        compute(kt & 3);
    }
    CP_WAIT0();

    // -------- epilogue --------
    #pragma unroll
    for (int i = 0; i < 4; i++) {
        const int rowA = row0 + wr * 64 + i * 16 + g;
        float p0a, p1a, p0b, p1b;
        if (MODE == 0) {
            p0a = probs[2 * rowA + expert];
            p0b = probs[2 * (rowA + 8) + expert];
            p1a = p1b = 0.f;
        } else {
            p0a = probs[2 * rowA];       p1a = probs[2 * rowA + 1];
            p0b = probs[2 * (rowA + 8)]; p1b = probs[2 * (rowA + 8) + 1];
        }
        #pragma unroll
        for (int j = 0; j < 8; j++) {
            const int col = col0 + wn * 64 + j * 8 + c * 2;
            OutT* out0 = C + (size_t)rowA * Nfeat + col;
            OutT* out1 = C + (size_t)(rowA + 8) * Nfeat + col;
            if (MODE == 0) {
                const float b0 = b0v[col], b1 = b0v[col + 1];
                *(__half2*)out0 = __floats2half2_rn(p0a * gelu_exact(acc[i][j][0] + b0),
                                                    p0a * gelu_exact(acc[i][j][1] + b1));
                *(__half2*)out1 = __floats2half2_rn(p0b * gelu_exact(acc[i][j][2] + b0),
                                                    p0b * gelu_exact(acc[i][j][3] + b1));
            } else {
                const float bl0 = b0v[col], bl1 = b0v[col + 1];
                const float bh0 = b1v[col], bh1 = b1v[col + 1];
                out0[0] = acc[i][j][0] + p0a * bl0 + p1a * bh0;
                out0[1] = acc[i][j][1] + p0a * bl1 + p1a * bh1;
                out1[0] = acc[i][j][2] + p0b * bl0 + p1b * bh0;
                out1[1] = acc[i][j][3] + p0b * bl1 + p1b * bh1;
            }
        }
    }
}

// -------------------- launch --------------------
extern "C" void kernel_launch(void* const* d_in, const int* in_sizes, int n_in,
                              void* d_out, int out_size) {
    const float* x        = (const float*)d_in[0];
    const float* router_w = (const float*)d_in[1];
    const float* router_b = (const float*)d_in[2];
    const float* light_w1 = (const float*)d_in[3];
    const float* light_b1 = (const float*)d_in[4];
    const float* light_w2 = (const float*)d_in[5];
    const float* light_b2 = (const float*)d_in[6];
    const float* heavy_w1 = (const float*)d_in[7];
    const float* heavy_b1 = (const float*)d_in[8];
    const float* heavy_w2 = (const float*)d_in[9];
    const float* heavy_b2 = (const float*)d_in[10];
    float* out = (float*)d_out;

    __half *hl, *hh, *xh, *lw1h, *hw1h, *lw2h, *hw2h;
    float* probs;
    cudaGetSymbolAddress((void**)&hl, g_hl);
    cudaGetSymbolAddress((void**)&hh, g_hh);
    cudaGetSymbolAddress((void**)&xh, g_xh);
    cudaGetSymbolAddress((void**)&lw1h, g_lw1h);
    cudaGetSymbolAddress((void**)&hw1h, g_hw1h);
    cudaGetSymbolAddress((void**)&lw2h, g_lw2h);
    cudaGetSymbolAddress((void**)&hw2h, g_hw2h);
    cudaGetSymbolAddress((void**)&probs, g_probs);

    static bool attr_done = false;
    if (!attr_done) {
        cudaFuncSetAttribute((const void*)gemm_f16_kernel<0, __half>,
                             cudaFuncAttributeMaxDynamicSharedMemorySize, SMEM_BYTES);
        cudaFuncSetAttribute((const void*)gemm_f16_kernel<1, float>,
                             cudaFuncAttributeMaxDynamicSharedMemorySize, SMEM_BYTES);
        attr_done = true;
    }

    router_kernel<<<N_TOK / 8, 256>>>(x, router_w, router_b, probs, xh);

    {   // weight conversions
        int n;
        n = LIGHT * HDIM / 4;  round16_kernel<<<(n + 255) / 256, 256>>>(light_w1, lw1h, n);
        n = HEAVY * HDIM / 4;  round16_kernel<<<(n + 255) / 256, 256>>>(heavy_w1, hw1h, n);
        n = HDIM * LIGHT / 4;  round16_kernel<<<(n + 255) / 256, 256>>>(light_w2, lw2h, n);
        n = HDIM * HEAVY / 4;  round16_kernel<<<(n + 255) / 256, 256>>>(heavy_w2, hw2h, n);
    }

    // fc1: hl = p0*gelu(x@lw1 + b), hh = p1*gelu(x@hw1 + b)   (fp16 out)
    {
        dim3 grid(LIGHT / 128, N_TOK / 256);
        gemm_f16_kernel<0, __half><<<grid, 256, SMEM_BYTES>>>(
            xh, lw1h, HDIM, nullptr, nullptr, 0, light_b1, nullptr, hl, probs, 0, LIGHT);
    }
    {
        dim3 grid(HEAVY / 128, N_TOK / 256);
        gemm_f16_kernel<0, __half><<<grid, 256, SMEM_BYTES>>>(
            xh, hw1h, HDIM, nullptr, nullptr, 0, heavy_b1, nullptr, hh, probs, 1, HEAVY);
    }
    // fc2 (dual segment): out = hl@lw2 + hh@hw2 + p0*b_l + p1*b_h
    {
        dim3 grid(HDIM / 128, N_TOK / 256);
        gemm_f16_kernel<1, float><<<grid, 256, SMEM_BYTES>>>(
            hl, lw2h, LIGHT, hh, hw2h, HEAVY, light_b2, heavy_b2, out, probs, 0, HDIM);
    }
}

// round 9
// speedup vs baseline: 1.0712x; 1.0712x over previous
#include <cuda_runtime.h>
#include <cuda_fp16.h>
#include <math.h>
#include <stdint.h>

// ---------------- problem constants ----------------
#define N_TOK 32768
#define HDIM  1152
#define LIGHT 1152
#define HEAVY 4608

// ---------------- static scratch (fp16 operands) ----------------
__device__ __half g_hl [(size_t)N_TOK * LIGHT];   // p0 * gelu(fc1_light)
__device__ __half g_hh [(size_t)N_TOK * HEAVY];   // p1 * gelu(fc1_heavy)
__device__ __half g_xh [(size_t)N_TOK * HDIM];
__device__ __half g_lw1h[(size_t)LIGHT * HDIM];
__device__ __half g_hw1h[(size_t)HEAVY * HDIM];
__device__ __half g_lw2h[(size_t)HDIM * LIGHT];
__device__ __half g_hw2h[(size_t)HDIM * HEAVY];
__device__ float  g_probs[2 * N_TOK];

__device__ __forceinline__ uint32_t smem_u32(const void* p) {
    uint32_t a;
    asm("{ .reg .u64 t; cvta.to.shared.u64 t, %1; cvt.u32.u64 %0, t; }" : "=r"(a) : "l"(p));
    return a;
}
__device__ __forceinline__ void cp_async16(uint32_t s, const void* g) {
    size_t gp = __cvta_generic_to_global(g);
    asm volatile("cp.async.cg.shared.global [%0], [%1], 16;" :: "r"(s), "l"(gp) : "memory");
}
#define CP_COMMIT() asm volatile("cp.async.commit_group;" ::: "memory")
#define CP_WAIT1()  asm volatile("cp.async.wait_group 1;" ::: "memory")
#define CP_WAIT0()  asm volatile("cp.async.wait_group 0;" ::: "memory")

__device__ __forceinline__ void ldmatrix_x4(uint32_t& r0, uint32_t& r1,
                                            uint32_t& r2, uint32_t& r3, uint32_t addr) {
    asm volatile("ldmatrix.sync.aligned.m8n8.x4.shared.b16 {%0,%1,%2,%3}, [%4];"
                 : "=r"(r0), "=r"(r1), "=r"(r2), "=r"(r3) : "r"(addr));
}
__device__ __forceinline__ void mma_f16(float* d, const uint32_t* a, const uint32_t* b) {
    asm volatile(
        "mma.sync.aligned.m16n8k16.row.col.f32.f16.f16.f32 "
        "{%0,%1,%2,%3}, {%4,%5,%6,%7}, {%8,%9}, {%0,%1,%2,%3};"
        : "+f"(d[0]), "+f"(d[1]), "+f"(d[2]), "+f"(d[3])
        : "r"(a[0]), "r"(a[1]), "r"(a[2]), "r"(a[3]), "r"(b[0]), "r"(b[1]));
}

__device__ __forceinline__ float gelu_exact(float v) {
    return 0.5f * v * (1.0f + erff(v * 0.70710678118654752f));
}

// -------------------- merged fp32 -> fp16 weight pre-round --------------------
__global__ void round16_all_kernel(const float* __restrict__ s0, __half* __restrict__ d0, int n0,
                                   const float* __restrict__ s1, __half* __restrict__ d1, int n1,
                                   const float* __restrict__ s2, __half* __restrict__ d2, int n2,
                                   const float* __restrict__ s3, __half* __restrict__ d3, int n3) {
    int i = blockIdx.x * blockDim.x + threadIdx.x;
    const float* s; __half* d;
    if (i < n0) { s = s0; d = d0; }
    else if ((i -= n0) < n1) { s = s1; d = d1; }
    else if ((i -= n1) < n2) { s = s2; d = d2; }
    else if ((i -= n2) < n3) { s = s3; d = d3; }
    else return;
    float4 v = ((const float4*)s)[i];
    ((__half2*)d)[2 * i]     = __floats2half2_rn(v.x, v.y);
    ((__half2*)d)[2 * i + 1] = __floats2half2_rn(v.z, v.w);
}

// -------------------- router (also converts x -> fp16) --------------------
__global__ void router_kernel(const float* __restrict__ x,
                              const float* __restrict__ rw,
                              const float* __restrict__ rb,
                              float* __restrict__ probs,
                              __half* __restrict__ xh) {
    int warp = (blockIdx.x * blockDim.x + threadIdx.x) >> 5;
    int lane = threadIdx.x & 31;
    if (warp >= N_TOK) return;
    const float* xp = x + (size_t)warp * HDIM;
    __half* xo = xh + (size_t)warp * HDIM;
    float a0 = 0.f, a1 = 0.f;
    #pragma unroll 4
    for (int h = lane; h < HDIM; h += 32) {
        float v = xp[h];
        xo[h] = __float2half_rn(v);
        a0 = fmaf(v, rw[h], a0);
        a1 = fmaf(v, rw[HDIM + h], a1);
    }
    #pragma unroll
    for (int off = 16; off; off >>= 1) {
        a0 += __shfl_xor_sync(0xffffffffu, a0, off);
        a1 += __shfl_xor_sync(0xffffffffu, a1, off);
    }
    if (lane == 0) {
        a0 += rb[0];
        a1 += rb[1];
        float m = fmaxf(a0, a1);
        float e0 = __expf(a0 - m), e1 = __expf(a1 - m);
        float inv = 1.0f / (e0 + e1);
        probs[2 * warp]     = e0 * inv;
        probs[2 * warp + 1] = e1 * inv;
    }
}

// -------------------- fp16 mma GEMM --------------------
// CTA 128x128, 128 threads, 4 warps (2x2), warp tile 64x64, BK=64,
// 3-stage cp.async, 96KB smem, 2 CTA/SM.
// Smem row = 64 halves = 128B; 16B-unit s stored at s ^ (row & 7).
// Fragment double-buffering across the 4 k-steps of each chunk.
// MODE 0 (fc1): C[fp16] = probs[n,expert] * gelu(acc + b0[m]);  single segment.
// MODE 1 (fc2): C[fp32] = acc(seg0) + acc(seg1) + p0*b0[m] + p1*b1[m]; dual segment.
#define STAGE_B 32768
#define SMEM_BYTES (3 * STAGE_B)

template <int MODE, typename OutT>
__global__ void __launch_bounds__(128, 2) gemm_f16_kernel(
    const __half* __restrict__ A0, const __half* __restrict__ W0, int K0,
    const __half* __restrict__ A1, const __half* __restrict__ W1, int K1,
    const float* __restrict__ b0v, const float* __restrict__ b1v,
    OutT* __restrict__ C, const float* __restrict__ probs, int expert, int Nfeat)
{
    extern __shared__ char smc[];
    const uint32_t sbase = smem_u32(smc);
    const int tid  = threadIdx.x;
    const int wid  = tid >> 5, lane = tid & 31;
    const int wr   = wid >> 1;      // 0..1 : 64-row group
    const int wn   = wid & 1;       // 0..1 : 64-col group
    const int g    = lane >> 2;     // 0..7
    const int c    = lane & 3;      // 0..3
    const int row0 = blockIdx.y * 128;
    const int col0 = blockIdx.x * 128;

    // ---- cp.async mapping: lrow=tid>>3 (0..15), ls=tid&7
    const int lrow = tid >> 3;
    const int ls   = tid & 7;
    const uint32_t offR = (uint32_t)(lrow * 128 + ((ls ^ (lrow & 7)) * 16));

    // ---- ldmatrix lane components
    const int arow = wr * 64 + (lane & 15);
    const int asel = lane >> 4;
    const int nrow = wn * 64 + (lane & 7) + ((lane >> 4) << 3);
    const int bsel = (lane >> 3) & 1;

    float acc[4][8][4];
    #pragma unroll
    for (int i = 0; i < 4; i++)
        #pragma unroll
        for (int j = 0; j < 8; j++)
            #pragma unroll
            for (int q = 0; q < 4; q++) acc[i][j][q] = 0.f;

    const int KT0 = K0 >> 6;
    const int KT  = KT0 + ((MODE == 1) ? (K1 >> 6) : 0);

    auto issue = [&](int kt) {
        const uint32_t so = (uint32_t)(kt % 3) * STAGE_B;
        const __half* a;
        const __half* w;
        int K;
        if (MODE == 0 || kt < KT0) {
            K = K0;
            a = A0 + (size_t)(row0 + lrow) * K0 + ls * 8 + kt * 64;
            w = W0 + (size_t)(col0 + lrow) * K0 + ls * 8 + kt * 64;
        } else {
            K = K1;
            int kl = kt - KT0;
            a = A1 + (size_t)(row0 + lrow) * K1 + ls * 8 + kl * 64;
            w = W1 + (size_t)(col0 + lrow) * K1 + ls * 8 + kl * 64;
        }
        #pragma unroll
        for (int i = 0; i < 8; i++) {
            cp_async16(sbase + so + offR + (uint32_t)i * 2048u,          a + (size_t)(i * 16) * K);
            cp_async16(sbase + so + 16384u + offR + (uint32_t)i * 2048u, w + (size_t)(i * 16) * K);
        }
    };

    auto ldfrags = [&](uint32_t as, uint32_t ws, int ks,
                       uint32_t af[4][4], uint32_t bf[4][4]) {
        const int ua = ks * 2 + asel;
        const int ub = ks * 2 + bsel;
        #pragma unroll
        for (int i = 0; i < 4; i++) {
            int r = arow + i * 16;
            uint32_t addr = as + (uint32_t)(r * 128 + ((ua ^ (arow & 7)) * 16));
            ldmatrix_x4(af[i][0], af[i][1], af[i][2], af[i][3], addr);
        }
        #pragma unroll
        for (int j2 = 0; j2 < 4; j2++) {
            int r = nrow + j2 * 16;
            uint32_t addr = ws + (uint32_t)(r * 128 + ((ub ^ (nrow & 7)) * 16));
            ldmatrix_x4(bf[j2][0], bf[j2][1], bf[j2][2], bf[j2][3], addr);
        }
    };

    auto compute = [&](int st) {
        const uint32_t as = sbase + (uint32_t)st * STAGE_B;
        const uint32_t ws = as + 16384u;
        uint32_t af[2][4][4], bf[2][4][4];
        ldfrags(as, ws, 0, af[0], bf[0]);
        #pragma unroll
        for (int ks = 0; ks < 4; ks++) {
            const int cur = ks & 1;
            if (ks < 3) ldfrags(as, ws, ks + 1, af[cur ^ 1], bf[cur ^ 1]);
            #pragma unroll
            for (int i = 0; i < 4; i++)
                #pragma unroll
                for (int j = 0; j < 8; j++)
                    mma_f16(acc[i][j], af[cur][i], &bf[cur][j >> 1][(j & 1) * 2]);
        }
    };

    issue(0); CP_COMMIT();
    issue(1); CP_COMMIT();
    for (int kt = 0; kt < KT; kt++) {
        CP_WAIT1();
        __syncthreads();
        if (kt + 2 < KT) issue(kt + 2);
        CP_COMMIT();
        compute(kt % 3);
    }
    CP_WAIT0();

    // -------- epilogue --------
    #pragma unroll
    for (int i = 0; i < 4; i++) {
        const int rowA = row0 + wr * 64 + i * 16 + g;
        float p0a, p1a, p0b, p1b;
        if (MODE == 0) {
            p0a = probs[2 * rowA + expert];
            p0b = probs[2 * (rowA + 8) + expert];
            p1a = p1b = 0.f;
        } else {
            p0a = probs[2 * rowA];       p1a = probs[2 * rowA + 1];
            p0b = probs[2 * (rowA + 8)]; p1b = probs[2 * (rowA + 8) + 1];
        }
        #pragma unroll
        for (int j = 0; j < 8; j++) {
            const int col = col0 + wn * 64 + j * 8 + c * 2;
            OutT* out0 = C + (size_t)rowA * Nfeat + col;
            OutT* out1 = C + (size_t)(rowA + 8) * Nfeat + col;
            if (MODE == 0) {
                const float b0 = b0v[col], b1 = b0v[col + 1];
                *(__half2*)out0 = __floats2half2_rn(p0a * gelu_exact(acc[i][j][0] + b0),
                                                    p0a * gelu_exact(acc[i][j][1] + b1));
                *(__half2*)out1 = __floats2half2_rn(p0b * gelu_exact(acc[i][j][2] + b0),
                                                    p0b * gelu_exact(acc[i][j][3] + b1));
            } else {
                const float bl0 = b0v[col], bl1 = b0v[col + 1];
                const float bh0 = b1v[col], bh1 = b1v[col + 1];
                out0[0] = acc[i][j][0] + p0a * bl0 + p1a * bh0;
                out0[1] = acc[i][j][1] + p0a * bl1 + p1a * bh1;
                out1[0] = acc[i][j][2] + p0b * bl0 + p1b * bh0;
                out1[1] = acc[i][j][3] + p0b * bl1 + p1b * bh1;
            }
        }
    }
}

// -------------------- launch --------------------
extern "C" void kernel_launch(void* const* d_in, const int* in_sizes, int n_in,
                              void* d_out, int out_size) {
    const float* x        = (const float*)d_in[0];
    const float* router_w = (const float*)d_in[1];
    const float* router_b = (const float*)d_in[2];
    const float* light_w1 = (const float*)d_in[3];
    const float* light_b1 = (const float*)d_in[4];
    const float* light_w2 = (const float*)d_in[5];
    const float* light_b2 = (const float*)d_in[6];
    const float* heavy_w1 = (const float*)d_in[7];
    const float* heavy_b1 = (const float*)d_in[8];
    const float* heavy_w2 = (const float*)d_in[9];
    const float* heavy_b2 = (const float*)d_in[10];
    float* out = (float*)d_out;

    __half *hl, *hh, *xh, *lw1h, *hw1h, *lw2h, *hw2h;
    float* probs;
    cudaGetSymbolAddress((void**)&hl, g_hl);
    cudaGetSymbolAddress((void**)&hh, g_hh);
    cudaGetSymbolAddress((void**)&xh, g_xh);
    cudaGetSymbolAddress((void**)&lw1h, g_lw1h);
    cudaGetSymbolAddress((void**)&hw1h, g_hw1h);
    cudaGetSymbolAddress((void**)&lw2h, g_lw2h);
    cudaGetSymbolAddress((void**)&hw2h, g_hw2h);
    cudaGetSymbolAddress((void**)&probs, g_probs);

    static bool attr_done = false;
    if (!attr_done) {
        cudaFuncSetAttribute((const void*)gemm_f16_kernel<0, __half>,
                             cudaFuncAttributeMaxDynamicSharedMemorySize, SMEM_BYTES);
        cudaFuncSetAttribute((const void*)gemm_f16_kernel<1, float>,
                             cudaFuncAttributeMaxDynamicSharedMemorySize, SMEM_BYTES);
        attr_done = true;
    }

    router_kernel<<<N_TOK / 8, 256>>>(x, router_w, router_b, probs, xh);

    {   // merged weight conversions
        const int n0 = LIGHT * HDIM / 4, n1 = HEAVY * HDIM / 4;
        const int n2 = HDIM * LIGHT / 4, n3 = HDIM * HEAVY / 4;
        const int total = n0 + n1 + n2 + n3;
        round16_all_kernel<<<(total + 255) / 256, 256>>>(
            light_w1, lw1h, n0, heavy_w1, hw1h, n1,
            light_w2, lw2h, n2, heavy_w2, hw2h, n3);
    }

    // fc1: hl = p0*gelu(x@lw1 + b), hh = p1*gelu(x@hw1 + b)   (fp16 out)
    {
        dim3 grid(LIGHT / 128, N_TOK / 128);
        gemm_f16_kernel<0, __half><<<grid, 128, SMEM_BYTES>>>(
            xh, lw1h, HDIM, nullptr, nullptr, 0, light_b1, nullptr, hl, probs, 0, LIGHT);
    }
    {
        dim3 grid(HEAVY / 128, N_TOK / 128);
        gemm_f16_kernel<0, __half><<<grid, 128, SMEM_BYTES>>>(
            xh, hw1h, HDIM, nullptr, nullptr, 0, heavy_b1, nullptr, hh, probs, 1, HEAVY);
    }
    // fc2 (dual segment): out = hl@lw2 + hh@hw2 + p0*b_l + p1*b_h
    {
        dim3 grid(HDIM / 128, N_TOK / 128);
        gemm_f16_kernel<1, float><<<grid, 128, SMEM_BYTES>>>(
            hl, lw2h, LIGHT, hh, hw2h, HEAVY, light_b2, heavy_b2, out, probs, 0, HDIM);
    }
}

// round 10
// speedup vs baseline: 1.0800x; 1.0082x over previous
#include <cuda_runtime.h>
#include <cuda_fp16.h>
#include <math.h>
#include <stdint.h>

// ---------------- problem constants ----------------
#define N_TOK 32768
#define HDIM  1152
#define LIGHT 1152
#define HEAVY 4608

// ---------------- static scratch (fp16 operands) ----------------
__device__ __half g_hl [(size_t)N_TOK * LIGHT];   // p0 * gelu(fc1_light)
__device__ __half g_hh [(size_t)N_TOK * HEAVY];   // p1 * gelu(fc1_heavy)
__device__ __half g_xh [(size_t)N_TOK * HDIM];
__device__ __half g_lw1h[(size_t)LIGHT * HDIM];
__device__ __half g_hw1h[(size_t)HEAVY * HDIM];
__device__ __half g_lw2h[(size_t)HDIM * LIGHT];
__device__ __half g_hw2h[(size_t)HDIM * HEAVY];
__device__ float  g_probs[2 * N_TOK];

__device__ __forceinline__ uint32_t smem_u32(const void* p) {
    uint32_t a;
    asm("{ .reg .u64 t; cvta.to.shared.u64 t, %1; cvt.u32.u64 %0, t; }" : "=r"(a) : "l"(p));
    return a;
}
__device__ __forceinline__ void cp_async16(uint32_t s, const void* g) {
    size_t gp = __cvta_generic_to_global(g);
    asm volatile("cp.async.cg.shared.global [%0], [%1], 16;" :: "r"(s), "l"(gp) : "memory");
}
#define CP_COMMIT() asm volatile("cp.async.commit_group;" ::: "memory")
#define CP_WAIT1()  asm volatile("cp.async.wait_group 1;" ::: "memory")
#define CP_WAIT0()  asm volatile("cp.async.wait_group 0;" ::: "memory")

__device__ __forceinline__ void ldmatrix_x4(uint32_t& r0, uint32_t& r1,
                                            uint32_t& r2, uint32_t& r3, uint32_t addr) {
    asm volatile("ldmatrix.sync.aligned.m8n8.x4.shared.b16 {%0,%1,%2,%3}, [%4];"
                 : "=r"(r0), "=r"(r1), "=r"(r2), "=r"(r3) : "r"(addr));
}
__device__ __forceinline__ void mma_f16(float* d, const uint32_t* a, const uint32_t* b) {
    asm volatile(
        "mma.sync.aligned.m16n8k16.row.col.f32.f16.f16.f32 "
        "{%0,%1,%2,%3}, {%4,%5,%6,%7}, {%8,%9}, {%0,%1,%2,%3};"
        : "+f"(d[0]), "+f"(d[1]), "+f"(d[2]), "+f"(d[3])
        : "r"(a[0]), "r"(a[1]), "r"(a[2]), "r"(a[3]), "r"(b[0]), "r"(b[1]));
}

__device__ __forceinline__ float gelu_exact(float v) {
    return 0.5f * v * (1.0f + erff(v * 0.70710678118654752f));
}

// -------------------- merged fp32 -> fp16 weight pre-round --------------------
__global__ void round16_all_kernel(const float* __restrict__ s0, __half* __restrict__ d0, int n0,
                                   const float* __restrict__ s1, __half* __restrict__ d1, int n1,
                                   const float* __restrict__ s2, __half* __restrict__ d2, int n2,
                                   const float* __restrict__ s3, __half* __restrict__ d3, int n3) {
    int i = blockIdx.x * blockDim.x + threadIdx.x;
    const float* s; __half* d;
    if (i < n0) { s = s0; d = d0; }
    else if ((i -= n0) < n1) { s = s1; d = d1; }
    else if ((i -= n1) < n2) { s = s2; d = d2; }
    else if ((i -= n2) < n3) { s = s3; d = d3; }
    else return;
    float4 v = ((const float4*)s)[i];
    ((__half2*)d)[2 * i]     = __floats2half2_rn(v.x, v.y);
    ((__half2*)d)[2 * i + 1] = __floats2half2_rn(v.z, v.w);
}

// -------------------- router (also converts x -> fp16) --------------------
__global__ void router_kernel(const float* __restrict__ x,
                              const float* __restrict__ rw,
                              const float* __restrict__ rb,
                              float* __restrict__ probs,
                              __half* __restrict__ xh) {
    int warp = (blockIdx.x * blockDim.x + threadIdx.x) >> 5;
    int lane = threadIdx.x & 31;
    if (warp >= N_TOK) return;
    const float* xp = x + (size_t)warp * HDIM;
    __half* xo = xh + (size_t)warp * HDIM;
    float a0 = 0.f, a1 = 0.f;
    #pragma unroll 4
    for (int h = lane; h < HDIM; h += 32) {
        float v = xp[h];
        xo[h] = __float2half_rn(v);
        a0 = fmaf(v, rw[h], a0);
        a1 = fmaf(v, rw[HDIM + h], a1);
    }
    #pragma unroll
    for (int off = 16; off; off >>= 1) {
        a0 += __shfl_xor_sync(0xffffffffu, a0, off);
        a1 += __shfl_xor_sync(0xffffffffu, a1, off);
    }
    if (lane == 0) {
        a0 += rb[0];
        a1 += rb[1];
        float m = fmaxf(a0, a1);
        float e0 = __expf(a0 - m), e1 = __expf(a1 - m);
        float inv = 1.0f / (e0 + e1);
        probs[2 * warp]     = e0 * inv;
        probs[2 * warp + 1] = e1 * inv;
    }
}

// -------------------- fp16 mma GEMM --------------------
// CTA 128x128, 128 threads, 4 warps (2x2), warp tile 64x64, BK=64,
// 3-stage cp.async, 96KB smem, 2 CTA/SM. Single-buffered fragments.
// Smem row = 64 halves = 128B; 16B-unit s stored at s ^ (row & 7).
// All ldmatrix address components hoisted to per-thread registers.
// MODE 0 (fc1): C[fp16] = probs[n,expert] * gelu(acc + b0[m]);  single segment.
// MODE 1 (fc2): C[fp32] = acc(seg0) + acc(seg1) + p0*b0[m] + p1*b1[m]; dual segment.
#define STAGE_B 32768
#define SMEM_BYTES (3 * STAGE_B)

template <int MODE, typename OutT>
__global__ void __launch_bounds__(128, 2) gemm_f16_kernel(
    const __half* __restrict__ A0, const __half* __restrict__ W0, int K0,
    const __half* __restrict__ A1, const __half* __restrict__ W1, int K1,
    const float* __restrict__ b0v, const float* __restrict__ b1v,
    OutT* __restrict__ C, const float* __restrict__ probs, int expert, int Nfeat)
{
    extern __shared__ char smc[];
    const uint32_t sbase = smem_u32(smc);
    const int tid  = threadIdx.x;
    const int wid  = tid >> 5, lane = tid & 31;
    const int wr   = wid >> 1;      // 0..1 : 64-row group
    const int wn   = wid & 1;       // 0..1 : 64-col group
    const int g    = lane >> 2;     // 0..7
    const int c    = lane & 3;      // 0..3
    const int row0 = blockIdx.y * 128;
    const int col0 = blockIdx.x * 128;

    // ---- cp.async mapping: lrow=tid>>3 (0..15), ls=tid&7
    const int lrow = tid >> 3;
    const int ls   = tid & 7;
    const uint32_t offR = (uint32_t)(lrow * 128 + ((ls ^ (lrow & 7)) * 16));

    // ---- hoisted ldmatrix address components (all loop-invariant per thread)
    const int arow = wr * 64 + (lane & 15);
    const int asel = lane >> 4;
    const int nrow = wn * 64 + (lane & 7) + ((lane >> 4) << 3);
    const int bsel = (lane >> 3) & 1;

    uint32_t aoff[4], boff[4], aperm[4], bperm[4];
    #pragma unroll
    for (int i = 0; i < 4; i++) {
        aoff[i] = (uint32_t)(arow * 128 + i * 2048);
        boff[i] = (uint32_t)(nrow * 128 + i * 2048);
    }
    #pragma unroll
    for (int ks = 0; ks < 4; ks++) {
        aperm[ks] = (uint32_t)((((ks * 2 + asel) ^ (arow & 7)) * 16));
        bperm[ks] = (uint32_t)((((ks * 2 + bsel) ^ (nrow & 7)) * 16));
    }

    float acc[4][8][4];
    #pragma unroll
    for (int i = 0; i < 4; i++)
        #pragma unroll
        for (int j = 0; j < 8; j++)
            #pragma unroll
            for (int q = 0; q < 4; q++) acc[i][j][q] = 0.f;

    const int KT0 = K0 >> 6;
    const int KT  = KT0 + ((MODE == 1) ? (K1 >> 6) : 0);

    auto issue = [&](int kt) {
        const uint32_t so = (uint32_t)(kt % 3) * STAGE_B;
        const __half* a;
        const __half* w;
        int K;
        if (MODE == 0 || kt < KT0) {
            K = K0;
            a = A0 + (size_t)(row0 + lrow) * K0 + ls * 8 + kt * 64;
            w = W0 + (size_t)(col0 + lrow) * K0 + ls * 8 + kt * 64;
        } else {
            K = K1;
            int kl = kt - KT0;
            a = A1 + (size_t)(row0 + lrow) * K1 + ls * 8 + kl * 64;
            w = W1 + (size_t)(col0 + lrow) * K1 + ls * 8 + kl * 64;
        }
        #pragma unroll
        for (int i = 0; i < 8; i++) {
            cp_async16(sbase + so + offR + (uint32_t)i * 2048u,          a + (size_t)(i * 16) * K);
            cp_async16(sbase + so + 16384u + offR + (uint32_t)i * 2048u, w + (size_t)(i * 16) * K);
        }
    };

    auto compute = [&](int st) {
        const uint32_t as = sbase + (uint32_t)st * STAGE_B;
        const uint32_t ws = as + 16384u;
        #pragma unroll
        for (int ks = 0; ks < 4; ks++) {
            uint32_t af[4][4], bf[4][4];
            #pragma unroll
            for (int i = 0; i < 4; i++)
                ldmatrix_x4(af[i][0], af[i][1], af[i][2], af[i][3],
                            as + aoff[i] + aperm[ks]);
            #pragma unroll
            for (int j2 = 0; j2 < 4; j2++)
                ldmatrix_x4(bf[j2][0], bf[j2][1], bf[j2][2], bf[j2][3],
                            ws + boff[j2] + bperm[ks]);
            #pragma unroll
            for (int i = 0; i < 4; i++)
                #pragma unroll
                for (int j = 0; j < 8; j++)
                    mma_f16(acc[i][j], af[i], &bf[j >> 1][(j & 1) * 2]);
        }
    };

    issue(0); CP_COMMIT();
    issue(1); CP_COMMIT();
    for (int kt = 0; kt < KT; kt++) {
        CP_WAIT1();
        __syncthreads();
        if (kt + 2 < KT) issue(kt + 2);
        CP_COMMIT();
        compute(kt % 3);
    }
    CP_WAIT0();

    // -------- epilogue --------
    #pragma unroll
    for (int i = 0; i < 4; i++) {
        const int rowA = row0 + wr * 64 + i * 16 + g;
        float p0a, p1a, p0b, p1b;
        if (MODE == 0) {
            p0a = probs[2 * rowA + expert];
            p0b = probs[2 * (rowA + 8) + expert];
            p1a = p1b = 0.f;
        } else {
            p0a = probs[2 * rowA];       p1a = probs[2 * rowA + 1];
            p0b = probs[2 * (rowA + 8)]; p1b = probs[2 * (rowA + 8) + 1];
        }
        #pragma unroll
        for (int j = 0; j < 8; j++) {
            const int col = col0 + wn * 64 + j * 8 + c * 2;
            OutT* out0 = C + (size_t)rowA * Nfeat + col;
            OutT* out1 = C + (size_t)(rowA + 8) * Nfeat + col;
            if (MODE == 0) {
                const float b0 = b0v[col], b1 = b0v[col + 1];
                *(__half2*)out0 = __floats2half2_rn(p0a * gelu_exact(acc[i][j][0] + b0),
                                                    p0a * gelu_exact(acc[i][j][1] + b1));
                *(__half2*)out1 = __floats2half2_rn(p0b * gelu_exact(acc[i][j][2] + b0),
                                                    p0b * gelu_exact(acc[i][j][3] + b1));
            } else {
                const float bl0 = b0v[col], bl1 = b0v[col + 1];
                const float bh0 = b1v[col], bh1 = b1v[col + 1];
                out0[0] = acc[i][j][0] + p0a * bl0 + p1a * bh0;
                out0[1] = acc[i][j][1] + p0a * bl1 + p1a * bh1;
                out1[0] = acc[i][j][2] + p0b * bl0 + p1b * bh0;
                out1[1] = acc[i][j][3] + p0b * bl1 + p1b * bh1;
            }
        }
    }
}

// -------------------- launch --------------------
extern "C" void kernel_launch(void* const* d_in, const int* in_sizes, int n_in,
                              void* d_out, int out_size) {
    const float* x        = (const float*)d_in[0];
    const float* router_w = (const float*)d_in[1];
    const float* router_b = (const float*)d_in[2];
    const float* light_w1 = (const float*)d_in[3];
    const float* light_b1 = (const float*)d_in[4];
    const float* light_w2 = (const float*)d_in[5];
    const float* light_b2 = (const float*)d_in[6];
    const float* heavy_w1 = (const float*)d_in[7];
    const float* heavy_b1 = (const float*)d_in[8];
    const float* heavy_w2 = (const float*)d_in[9];
    const float* heavy_b2 = (const float*)d_in[10];
    float* out = (float*)d_out;

    __half *hl, *hh, *xh, *lw1h, *hw1h, *lw2h, *hw2h;
    float* probs;
    cudaGetSymbolAddress((void**)&hl, g_hl);
    cudaGetSymbolAddress((void**)&hh, g_hh);
    cudaGetSymbolAddress((void**)&xh, g_xh);
    cudaGetSymbolAddress((void**)&lw1h, g_lw1h);
    cudaGetSymbolAddress((void**)&hw1h, g_hw1h);
    cudaGetSymbolAddress((void**)&lw2h, g_lw2h);
    cudaGetSymbolAddress((void**)&hw2h, g_hw2h);
    cudaGetSymbolAddress((void**)&probs, g_probs);

    static bool attr_done = false;
    if (!attr_done) {
        cudaFuncSetAttribute((const void*)gemm_f16_kernel<0, __half>,
                             cudaFuncAttributeMaxDynamicSharedMemorySize, SMEM_BYTES);
        cudaFuncSetAttribute((const void*)gemm_f16_kernel<1, float>,
                             cudaFuncAttributeMaxDynamicSharedMemorySize, SMEM_BYTES);
        attr_done = true;
    }

    router_kernel<<<N_TOK / 8, 256>>>(x, router_w, router_b, probs, xh);

    {   // merged weight conversions
        const int n0 = LIGHT * HDIM / 4, n1 = HEAVY * HDIM / 4;
        const int n2 = HDIM * LIGHT / 4, n3 = HDIM * HEAVY / 4;
        const int total = n0 + n1 + n2 + n3;
        round16_all_kernel<<<(total + 255) / 256, 256>>>(
            light_w1, lw1h, n0, heavy_w1, hw1h, n1,
            light_w2, lw2h, n2, heavy_w2, hw2h, n3);
    }

    // fc1: hl = p0*gelu(x@lw1 + b), hh = p1*gelu(x@hw1 + b)   (fp16 out)
    {
        dim3 grid(LIGHT / 128, N_TOK / 128);
        gemm_f16_kernel<0, __half><<<grid, 128, SMEM_BYTES>>>(
            xh, lw1h, HDIM, nullptr, nullptr, 0, light_b1, nullptr, hl, probs, 0, LIGHT);
    }
    {
        dim3 grid(HEAVY / 128, N_TOK / 128);
        gemm_f16_kernel<0, __half><<<grid, 128, SMEM_BYTES>>>(
            xh, hw1h, HDIM, nullptr, nullptr, 0, heavy_b1, nullptr, hh, probs, 1, HEAVY);
    }
    // fc2 (dual segment): out = hl@lw2 + hh@hw2 + p0*b_l + p1*b_h
    {
        dim3 grid(HDIM / 128, N_TOK / 128);
        gemm_f16_kernel<1, float><<<grid, 128, SMEM_BYTES>>>(
            hl, lw2h, LIGHT, hh, hw2h, HEAVY, light_b2, heavy_b2, out, probs, 0, HDIM);
    }
}

// round 11
// speedup vs baseline: 1.1435x; 1.0587x over previous
#include <cuda_runtime.h>
#include <cuda_fp16.h>
#include <math.h>
#include <stdint.h>

// ---------------- problem constants ----------------
#define N_TOK 32768
#define HDIM  1152
#define LIGHT 1152
#define HEAVY 4608

// ---------------- static scratch (fp16 operands) ----------------
__device__ __half g_hl [(size_t)N_TOK * LIGHT];   // p0 * gelu(fc1_light)
__device__ __half g_hh [(size_t)N_TOK * HEAVY];   // p1 * gelu(fc1_heavy)
__device__ __half g_xh [(size_t)N_TOK * HDIM];
__device__ __half g_lw1h[(size_t)LIGHT * HDIM];
__device__ __half g_hw1h[(size_t)HEAVY * HDIM];
__device__ __half g_lw2h[(size_t)HDIM * LIGHT];
__device__ __half g_hw2h[(size_t)HDIM * HEAVY];
__device__ float  g_probs[2 * N_TOK];

__device__ __forceinline__ uint32_t smem_u32(const void* p) {
    uint32_t a;
    asm("{ .reg .u64 t; cvta.to.shared.u64 t, %1; cvt.u32.u64 %0, t; }" : "=r"(a) : "l"(p));
    return a;
}
__device__ __forceinline__ void cp_async16(uint32_t s, const void* g) {
    size_t gp = __cvta_generic_to_global(g);
    asm volatile("cp.async.cg.shared.global [%0], [%1], 16;" :: "r"(s), "l"(gp) : "memory");
}
#define CP_COMMIT() asm volatile("cp.async.commit_group;" ::: "memory")
#define CP_WAIT1()  asm volatile("cp.async.wait_group 1;" ::: "memory")
#define CP_WAIT0()  asm volatile("cp.async.wait_group 0;" ::: "memory")

__device__ __forceinline__ void ldmatrix_x4(uint32_t& r0, uint32_t& r1,
                                            uint32_t& r2, uint32_t& r3, uint32_t addr) {
    asm volatile("ldmatrix.sync.aligned.m8n8.x4.shared.b16 {%0,%1,%2,%3}, [%4];"
                 : "=r"(r0), "=r"(r1), "=r"(r2), "=r"(r3) : "r"(addr));
}
__device__ __forceinline__ void mma_f16(float* d, const uint32_t* a, const uint32_t* b) {
    asm volatile(
        "mma.sync.aligned.m16n8k16.row.col.f32.f16.f16.f32 "
        "{%0,%1,%2,%3}, {%4,%5,%6,%7}, {%8,%9}, {%0,%1,%2,%3};"
        : "+f"(d[0]), "+f"(d[1]), "+f"(d[2]), "+f"(d[3])
        : "r"(a[0]), "r"(a[1]), "r"(a[2]), "r"(a[3]), "r"(b[0]), "r"(b[1]));
}

__device__ __forceinline__ float gelu_exact(float v) {
    return 0.5f * v * (1.0f + erff(v * 0.70710678118654752f));
}

// -------------------- merged fp32 -> fp16 weight pre-round --------------------
__global__ void round16_all_kernel(const float* __restrict__ s0, __half* __restrict__ d0, int n0,
                                   const float* __restrict__ s1, __half* __restrict__ d1, int n1,
                                   const float* __restrict__ s2, __half* __restrict__ d2, int n2,
                                   const float* __restrict__ s3, __half* __restrict__ d3, int n3) {
    int i = blockIdx.x * blockDim.x + threadIdx.x;
    const float* s; __half* d;
    if (i < n0) { s = s0; d = d0; }
    else if ((i -= n0) < n1) { s = s1; d = d1; }
    else if ((i -= n1) < n2) { s = s2; d = d2; }
    else if ((i -= n2) < n3) { s = s3; d = d3; }
    else return;
    float4 v = ((const float4*)s)[i];
    ((__half2*)d)[2 * i]     = __floats2half2_rn(v.x, v.y);
    ((__half2*)d)[2 * i + 1] = __floats2half2_rn(v.z, v.w);
}

// -------------------- router (also converts x -> fp16) --------------------
__global__ void router_kernel(const float* __restrict__ x,
                              const float* __restrict__ rw,
                              const float* __restrict__ rb,
                              float* __restrict__ probs,
                              __half* __restrict__ xh) {
    int warp = (blockIdx.x * blockDim.x + threadIdx.x) >> 5;
    int lane = threadIdx.x & 31;
    if (warp >= N_TOK) return;
    const float* xp = x + (size_t)warp * HDIM;
    __half* xo = xh + (size_t)warp * HDIM;
    float a0 = 0.f, a1 = 0.f;
    #pragma unroll 4
    for (int h = lane; h < HDIM; h += 32) {
        float v = xp[h];
        xo[h] = __float2half_rn(v);
        a0 = fmaf(v, rw[h], a0);
        a1 = fmaf(v, rw[HDIM + h], a1);
    }
    #pragma unroll
    for (int off = 16; off; off >>= 1) {
        a0 += __shfl_xor_sync(0xffffffffu, a0, off);
        a1 += __shfl_xor_sync(0xffffffffu, a1, off);
    }
    if (lane == 0) {
        a0 += rb[0];
        a1 += rb[1];
        float m = fmaxf(a0, a1);
        float e0 = __expf(a0 - m), e1 = __expf(a1 - m);
        float inv = 1.0f / (e0 + e1);
        probs[2 * warp]     = e0 * inv;
        probs[2 * warp + 1] = e1 * inv;
    }
}

// -------------------- fp16 mma GEMM --------------------
// CTA 128x128, 128 threads, 4 warps (2x2), warp tile 64x64, BK=64,
// 3-stage cp.async, 96KB smem, 2 CTA/SM.
// Persistent global pointers (advance by 64 halves/chunk) - no per-chunk
// address recomputation. Per k-step: 4 B-ldsm then ping-pong A-ldsm
// interleaved with mma rows.
// MODE 0 (fc1): C[fp16] = probs[n,expert] * gelu(acc + b0[m]);  single segment.
// MODE 1 (fc2): C[fp32] = acc(seg0) + acc(seg1) + p0*b0[m] + p1*b1[m]; dual segment.
#define STAGE_B 32768u
#define SMEM_BYTES (3 * 32768)

template <int MODE, typename OutT>
__global__ void __launch_bounds__(128, 2) gemm_f16_kernel(
    const __half* __restrict__ A0, const __half* __restrict__ W0, int K0,
    const __half* __restrict__ A1, const __half* __restrict__ W1, int K1,
    const float* __restrict__ b0v, const float* __restrict__ b1v,
    OutT* __restrict__ C, const float* __restrict__ probs, int expert, int Nfeat)
{
    extern __shared__ char smc[];
    const uint32_t sbase = smem_u32(smc);
    const int tid  = threadIdx.x;
    const int wid  = tid >> 5, lane = tid & 31;
    const int wr   = wid >> 1;      // 0..1 : 64-row group
    const int wn   = wid & 1;       // 0..1 : 64-col group
    const int g    = lane >> 2;     // 0..7
    const int c    = lane & 3;      // 0..3
    const int row0 = blockIdx.y * 128;
    const int col0 = blockIdx.x * 128;

    // ---- cp.async smem destination (fixed per thread, plus rotating stage)
    const int lrow = tid >> 3;      // 0..15
    const int ls   = tid & 7;       // 16B unit
    const uint32_t offR = (uint32_t)(lrow * 128 + ((ls ^ (lrow & 7)) * 16));

    // ---- persistent global source pointers (advance 64 halves per chunk)
    const __half* pa = A0 + (size_t)(row0 + lrow) * K0 + ls * 8;
    const __half* pw = W0 + (size_t)(col0 + lrow) * K0 + ls * 8;
    size_t rs = (size_t)16 * K0;    // 16-row stride in elements

    // ---- ldmatrix lane components
    const int arow = wr * 64 + (lane & 15);
    const int asel = lane >> 4;
    const int nrow = wn * 64 + (lane & 7) + ((lane >> 4) << 3);
    const int bsel = (lane >> 3) & 1;

    float acc[4][8][4];
    #pragma unroll
    for (int i = 0; i < 4; i++)
        #pragma unroll
        for (int j = 0; j < 8; j++)
            #pragma unroll
            for (int q = 0; q < 4; q++) acc[i][j][q] = 0.f;

    const int KT0 = K0 >> 6;
    const int KT  = KT0 + ((MODE == 1) ? (K1 >> 6) : 0);

    int issued = 0;
    uint32_t so = 0;                // issue-side stage offset
    auto issue_next = [&]() {
        if (MODE == 1 && issued == KT0) {   // switch to segment 1
            pa = A1 + (size_t)(row0 + lrow) * K1 + ls * 8;
            pw = W1 + (size_t)(col0 + lrow) * K1 + ls * 8;
            rs = (size_t)16 * K1;
        }
        #pragma unroll
        for (int i = 0; i < 8; i++) {
            cp_async16(sbase + so + offR + (uint32_t)i * 2048u,          pa + (size_t)i * rs);
            cp_async16(sbase + so + 16384u + offR + (uint32_t)i * 2048u, pw + (size_t)i * rs);
        }
        pa += 64; pw += 64;
        issued++;
        so += STAGE_B; if (so == 3 * STAGE_B) so = 0;
    };

    auto compute = [&](uint32_t co) {
        const uint32_t as = sbase + co;
        const uint32_t ws = as + 16384u;
        #pragma unroll
        for (int ks = 0; ks < 4; ks++) {
            const uint32_t pb = (uint32_t)((((ks * 2 + bsel) ^ (nrow & 7)) * 16));
            const uint32_t paoff = (uint32_t)((((ks * 2 + asel) ^ (arow & 7)) * 16));
            uint32_t bf[4][4];
            #pragma unroll
            for (int j2 = 0; j2 < 4; j2++)
                ldmatrix_x4(bf[j2][0], bf[j2][1], bf[j2][2], bf[j2][3],
                            ws + (uint32_t)(nrow * 128 + j2 * 2048) + pb);
            uint32_t afa[4], afb[4];
            const uint32_t abase = as + (uint32_t)(arow * 128) + paoff;
            ldmatrix_x4(afa[0], afa[1], afa[2], afa[3], abase);
            // i = 0
            ldmatrix_x4(afb[0], afb[1], afb[2], afb[3], abase + 2048u);
            #pragma unroll
            for (int j = 0; j < 8; j++) mma_f16(acc[0][j], afa, &bf[j >> 1][(j & 1) * 2]);
            // i = 1
            ldmatrix_x4(afa[0], afa[1], afa[2], afa[3], abase + 4096u);
            #pragma unroll
            for (int j = 0; j < 8; j++) mma_f16(acc[1][j], afb, &bf[j >> 1][(j & 1) * 2]);
            // i = 2
            ldmatrix_x4(afb[0], afb[1], afb[2], afb[3], abase + 6144u);
            #pragma unroll
            for (int j = 0; j < 8; j++) mma_f16(acc[2][j], afa, &bf[j >> 1][(j & 1) * 2]);
            // i = 3
            #pragma unroll
            for (int j = 0; j < 8; j++) mma_f16(acc[3][j], afb, &bf[j >> 1][(j & 1) * 2]);
        }
    };

    issue_next(); CP_COMMIT();
    issue_next(); CP_COMMIT();
    uint32_t co = 0;
    for (int kt = 0; kt < KT; kt++) {
        CP_WAIT1();
        __syncthreads();
        if (kt + 2 < KT) issue_next();
        CP_COMMIT();
        compute(co);
        co += STAGE_B; if (co == 3 * STAGE_B) co = 0;
    }
    CP_WAIT0();

    // -------- epilogue --------
    #pragma unroll
    for (int i = 0; i < 4; i++) {
        const int rowA = row0 + wr * 64 + i * 16 + g;
        float p0a, p1a, p0b, p1b;
        if (MODE == 0) {
            p0a = probs[2 * rowA + expert];
            p0b = probs[2 * (rowA + 8) + expert];
            p1a = p1b = 0.f;
        } else {
            p0a = probs[2 * rowA];       p1a = probs[2 * rowA + 1];
            p0b = probs[2 * (rowA + 8)]; p1b = probs[2 * (rowA + 8) + 1];
        }
        #pragma unroll
        for (int j = 0; j < 8; j++) {
            const int col = col0 + wn * 64 + j * 8 + c * 2;
            OutT* out0 = C + (size_t)rowA * Nfeat + col;
            OutT* out1 = C + (size_t)(rowA + 8) * Nfeat + col;
            if (MODE == 0) {
                const float b0 = b0v[col], b1 = b0v[col + 1];
                *(__half2*)out0 = __floats2half2_rn(p0a * gelu_exact(acc[i][j][0] + b0),
                                                    p0a * gelu_exact(acc[i][j][1] + b1));
                *(__half2*)out1 = __floats2half2_rn(p0b * gelu_exact(acc[i][j][2] + b0),
                                                    p0b * gelu_exact(acc[i][j][3] + b1));
            } else {
                const float bl0 = b0v[col], bl1 = b0v[col + 1];
                const float bh0 = b1v[col], bh1 = b1v[col + 1];
                out0[0] = acc[i][j][0] + p0a * bl0 + p1a * bh0;
                out0[1] = acc[i][j][1] + p0a * bl1 + p1a * bh1;
                out1[0] = acc[i][j][2] + p0b * bl0 + p1b * bh0;
                out1[1] = acc[i][j][3] + p0b * bl1 + p1b * bh1;
            }
        }
    }
}

// -------------------- launch --------------------
extern "C" void kernel_launch(void* const* d_in, const int* in_sizes, int n_in,
                              void* d_out, int out_size) {
    const float* x        = (const float*)d_in[0];
    const float* router_w = (const float*)d_in[1];
    const float* router_b = (const float*)d_in[2];
    const float* light_w1 = (const float*)d_in[3];
    const float* light_b1 = (const float*)d_in[4];
    const float* light_w2 = (const float*)d_in[5];
    const float* light_b2 = (const float*)d_in[6];
    const float* heavy_w1 = (const float*)d_in[7];
    const float* heavy_b1 = (const float*)d_in[8];
    const float* heavy_w2 = (const float*)d_in[9];
    const float* heavy_b2 = (const float*)d_in[10];
    float* out = (float*)d_out;

    __half *hl, *hh, *xh, *lw1h, *hw1h, *lw2h, *hw2h;
    float* probs;
    cudaGetSymbolAddress((void**)&hl, g_hl);
    cudaGetSymbolAddress((void**)&hh, g_hh);
    cudaGetSymbolAddress((void**)&xh, g_xh);
    cudaGetSymbolAddress((void**)&lw1h, g_lw1h);
    cudaGetSymbolAddress((void**)&hw1h, g_hw1h);
    cudaGetSymbolAddress((void**)&lw2h, g_lw2h);
    cudaGetSymbolAddress((void**)&hw2h, g_hw2h);
    cudaGetSymbolAddress((void**)&probs, g_probs);

    static bool attr_done = false;
    if (!attr_done) {
        cudaFuncSetAttribute((const void*)gemm_f16_kernel<0, __half>,
                             cudaFuncAttributeMaxDynamicSharedMemorySize, SMEM_BYTES);
        cudaFuncSetAttribute((const void*)gemm_f16_kernel<1, float>,
                             cudaFuncAttributeMaxDynamicSharedMemorySize, SMEM_BYTES);
        attr_done = true;
    }

    router_kernel<<<N_TOK / 8, 256>>>(x, router_w, router_b, probs, xh);

    {   // merged weight conversions
        const int n0 = LIGHT * HDIM / 4, n1 = HEAVY * HDIM / 4;
        const int n2 = HDIM * LIGHT / 4, n3 = HDIM * HEAVY / 4;
        const int total = n0 + n1 + n2 + n3;
        round16_all_kernel<<<(total + 255) / 256, 256>>>(
            light_w1, lw1h, n0, heavy_w1, hw1h, n1,
            light_w2, lw2h, n2, heavy_w2, hw2h, n3);
    }

    // fc1: hl = p0*gelu(x@lw1 + b), hh = p1*gelu(x@hw1 + b)   (fp16 out)
    {
        dim3 grid(LIGHT / 128, N_TOK / 128);
        gemm_f16_kernel<0, __half><<<grid, 128, SMEM_BYTES>>>(
            xh, lw1h, HDIM, nullptr, nullptr, 0, light_b1, nullptr, hl, probs, 0, LIGHT);
    }
    {
        dim3 grid(HEAVY / 128, N_TOK / 128);
        gemm_f16_kernel<0, __half><<<grid, 128, SMEM_BYTES>>>(
            xh, hw1h, HDIM, nullptr, nullptr, 0, heavy_b1, nullptr, hh, probs, 1, HEAVY);
    }
    // fc2 (dual segment): out = hl@lw2 + hh@hw2 + p0*b_l + p1*b_h
    {
        dim3 grid(HDIM / 128, N_TOK / 128);
        gemm_f16_kernel<1, float><<<grid, 128, SMEM_BYTES>>>(
            hl, lw2h, LIGHT, hh, hw2h, HEAVY, light_b2, heavy_b2, out, probs, 0, HDIM);
    }
}

// round 12
// speedup vs baseline: 1.1532x; 1.0085x over previous
#include <cuda_runtime.h>
#include <cuda_fp16.h>
#include <math.h>
#include <stdint.h>

// ---------------- problem constants ----------------
#define N_TOK 32768
#define HDIM  1152
#define LIGHT 1152
#define HEAVY 4608

// ---------------- static scratch (fp16 operands) ----------------
__device__ __half g_hl [(size_t)N_TOK * LIGHT];   // p0 * gelu(fc1_light)
__device__ __half g_hh [(size_t)N_TOK * HEAVY];   // p1 * gelu(fc1_heavy)
__device__ __half g_xh [(size_t)N_TOK * HDIM];
__device__ __half g_lw1h[(size_t)LIGHT * HDIM];
__device__ __half g_hw1h[(size_t)HEAVY * HDIM];
__device__ __half g_lw2h[(size_t)HDIM * LIGHT];
__device__ __half g_hw2h[(size_t)HDIM * HEAVY];
__device__ float  g_probs[2 * N_TOK];

__device__ __forceinline__ uint32_t smem_u32(const void* p) {
    uint32_t a;
    asm("{ .reg .u64 t; cvta.to.shared.u64 t, %1; cvt.u32.u64 %0, t; }" : "=r"(a) : "l"(p));
    return a;
}
__device__ __forceinline__ void cp_async16(uint32_t s, const void* g) {
    size_t gp = __cvta_generic_to_global(g);
    asm volatile("cp.async.cg.shared.global [%0], [%1], 16;" :: "r"(s), "l"(gp) : "memory");
}
#define CP_COMMIT() asm volatile("cp.async.commit_group;" ::: "memory")
#define CP_WAIT1()  asm volatile("cp.async.wait_group 1;" ::: "memory")
#define CP_WAIT0()  asm volatile("cp.async.wait_group 0;" ::: "memory")

__device__ __forceinline__ void ldmatrix_x4(uint32_t& r0, uint32_t& r1,
                                            uint32_t& r2, uint32_t& r3, uint32_t addr) {
    asm volatile("ldmatrix.sync.aligned.m8n8.x4.shared.b16 {%0,%1,%2,%3}, [%4];"
                 : "=r"(r0), "=r"(r1), "=r"(r2), "=r"(r3) : "r"(addr));
}
__device__ __forceinline__ void mma_f16(float* d, const uint32_t* a, const uint32_t* b) {
    asm volatile(
        "mma.sync.aligned.m16n8k16.row.col.f32.f16.f16.f32 "
        "{%0,%1,%2,%3}, {%4,%5,%6,%7}, {%8,%9}, {%0,%1,%2,%3};"
        : "+f"(d[0]), "+f"(d[1]), "+f"(d[2]), "+f"(d[3])
        : "r"(a[0]), "r"(a[1]), "r"(a[2]), "r"(a[3]), "r"(b[0]), "r"(b[1]));
}

__device__ __forceinline__ float gelu_exact(float v) {
    return 0.5f * v * (1.0f + erff(v * 0.70710678118654752f));
}

// -------------------- merged fp32 -> fp16 weight pre-round --------------------
__global__ void round16_all_kernel(const float* __restrict__ s0, __half* __restrict__ d0, int n0,
                                   const float* __restrict__ s1, __half* __restrict__ d1, int n1,
                                   const float* __restrict__ s2, __half* __restrict__ d2, int n2,
                                   const float* __restrict__ s3, __half* __restrict__ d3, int n3) {
    int i = blockIdx.x * blockDim.x + threadIdx.x;
    const float* s; __half* d;
    if (i < n0) { s = s0; d = d0; }
    else if ((i -= n0) < n1) { s = s1; d = d1; }
    else if ((i -= n1) < n2) { s = s2; d = d2; }
    else if ((i -= n2) < n3) { s = s3; d = d3; }
    else return;
    float4 v = ((const float4*)s)[i];
    ((__half2*)d)[2 * i]     = __floats2half2_rn(v.x, v.y);
    ((__half2*)d)[2 * i + 1] = __floats2half2_rn(v.z, v.w);
}

// -------------------- router (also converts x -> fp16) --------------------
__global__ void router_kernel(const float* __restrict__ x,
                              const float* __restrict__ rw,
                              const float* __restrict__ rb,
                              float* __restrict__ probs,
                              __half* __restrict__ xh) {
    int warp = (blockIdx.x * blockDim.x + threadIdx.x) >> 5;
    int lane = threadIdx.x & 31;
    if (warp >= N_TOK) return;
    const float* xp = x + (size_t)warp * HDIM;
    __half* xo = xh + (size_t)warp * HDIM;
    float a0 = 0.f, a1 = 0.f;
    #pragma unroll 4
    for (int h = lane; h < HDIM; h += 32) {
        float v = xp[h];
        xo[h] = __float2half_rn(v);
        a0 = fmaf(v, rw[h], a0);
        a1 = fmaf(v, rw[HDIM + h], a1);
    }
    #pragma unroll
    for (int off = 16; off; off >>= 1) {
        a0 += __shfl_xor_sync(0xffffffffu, a0, off);
        a1 += __shfl_xor_sync(0xffffffffu, a1, off);
    }
    if (lane == 0) {
        a0 += rb[0];
        a1 += rb[1];
        float m = fmaxf(a0, a1);
        float e0 = __expf(a0 - m), e1 = __expf(a1 - m);
        float inv = 1.0f / (e0 + e1);
        probs[2 * warp]     = e0 * inv;
        probs[2 * warp + 1] = e1 * inv;
    }
}

// -------------------- fp16 mma GEMM --------------------
// CTA 128x128, 128 threads, 4 warps (2x2), warp tile 64x64, BK=64,
// 3-stage cp.async, 96KB smem, 2 CTA/SM. Persistent global pointers.
// Cross-k-step fragment double-buffering (A and B): prefetch k-step ks+1's
// 8 ldsm before the 32 mma of step ks.
// MODE 0 (merged fc1): blockIdx.x < 9 -> light expert, else heavy.
//        C[fp16] = probs[n,expert] * gelu(acc + bias[m]).
// MODE 1 (fc2): C[fp32] = acc(seg0) + acc(seg1) + p0*b0[m] + p1*b1[m].
#define STAGE_B 32768u
#define SMEM_BYTES (3 * 32768)

template <int MODE, typename OutT>
__global__ void __launch_bounds__(128, 2) gemm_f16_kernel(
    const __half* __restrict__ A0, const __half* __restrict__ W0, int K0,
    const __half* __restrict__ A1, const __half* __restrict__ W1, int K1,
    const float* __restrict__ b0v, const float* __restrict__ b1v,
    OutT* __restrict__ C, OutT* __restrict__ C2,
    const float* __restrict__ probs, int ncol_light)
{
    extern __shared__ char smc[];
    const uint32_t sbase = smem_u32(smc);
    const int tid  = threadIdx.x;
    const int wid  = tid >> 5, lane = tid & 31;
    const int wr   = wid >> 1;      // 0..1 : 64-row group
    const int wn   = wid & 1;       // 0..1 : 64-col group
    const int g    = lane >> 2;     // 0..7
    const int c    = lane & 3;      // 0..3
    const int row0 = blockIdx.y * 128;

    // ---- MODE 0: select expert by column-tile index
    const __half* Wsel = W0;
    const float*  bsel = b0v;
    OutT*         Csel = C;
    int           Nfeat, expert, colt;
    if (MODE == 0) {
        if ((int)blockIdx.x < ncol_light) {
            colt = blockIdx.x;              Nfeat = LIGHT; expert = 0;
        } else {
            colt = blockIdx.x - ncol_light; Nfeat = HEAVY; expert = 1;
            Wsel = W1; bsel = b1v; Csel = C2;
        }
    } else {
        colt = blockIdx.x; Nfeat = HDIM; expert = 0;
    }
    const int col0 = colt * 128;

    // ---- cp.async smem destination
    const int lrow = tid >> 3;      // 0..15
    const int ls   = tid & 7;       // 16B unit
    const uint32_t offR = (uint32_t)(lrow * 128 + ((ls ^ (lrow & 7)) * 16));

    // ---- persistent global source pointers
    const __half* pa = A0 + (size_t)(row0 + lrow) * K0 + ls * 8;
    const __half* pw = Wsel + (size_t)(col0 + lrow) * K0 + ls * 8;
    size_t rs = (size_t)16 * K0;

    // ---- ldmatrix lane components
    const int arow = wr * 64 + (lane & 15);
    const int asel = lane >> 4;
    const int nrow = wn * 64 + (lane & 7) + ((lane >> 4) << 3);
    const int bsel2 = (lane >> 3) & 1;

    float acc[4][8][4];
    #pragma unroll
    for (int i = 0; i < 4; i++)
        #pragma unroll
        for (int j = 0; j < 8; j++)
            #pragma unroll
            for (int q = 0; q < 4; q++) acc[i][j][q] = 0.f;

    const int KT0 = K0 >> 6;
    const int KT  = KT0 + ((MODE == 1) ? (K1 >> 6) : 0);

    int issued = 0;
    uint32_t so = 0;
    auto issue_next = [&]() {
        if (MODE == 1 && issued == KT0) {
            pa = A1 + (size_t)(row0 + lrow) * K1 + ls * 8;
            pw = W1 + (size_t)(col0 + lrow) * K1 + ls * 8;
            rs = (size_t)16 * K1;
        }
        #pragma unroll
        for (int i = 0; i < 8; i++) {
            cp_async16(sbase + so + offR + (uint32_t)i * 2048u,          pa + (size_t)i * rs);
            cp_async16(sbase + so + 16384u + offR + (uint32_t)i * 2048u, pw + (size_t)i * rs);
        }
        pa += 64; pw += 64;
        issued++;
        so += STAGE_B; if (so == 3 * STAGE_B) so = 0;
    };

    // fragment loaders for one k-step
    auto ldA = [&](uint32_t as, int ks, uint32_t af[4][4]) {
        const uint32_t p = (uint32_t)((((ks * 2 + asel) ^ (arow & 7)) * 16));
        const uint32_t base = as + (uint32_t)(arow * 128) + p;
        #pragma unroll
        for (int i = 0; i < 4; i++)
            ldmatrix_x4(af[i][0], af[i][1], af[i][2], af[i][3], base + (uint32_t)(i * 2048));
    };
    auto ldB = [&](uint32_t ws, int ks, uint32_t bf[4][4]) {
        const uint32_t p = (uint32_t)((((ks * 2 + bsel2) ^ (nrow & 7)) * 16));
        const uint32_t base = ws + (uint32_t)(nrow * 128) + p;
        #pragma unroll
        for (int j2 = 0; j2 < 4; j2++)
            ldmatrix_x4(bf[j2][0], bf[j2][1], bf[j2][2], bf[j2][3], base + (uint32_t)(j2 * 2048));
    };

    auto compute = [&](uint32_t co) {
        const uint32_t as = sbase + co;
        const uint32_t ws = as + 16384u;
        uint32_t af[2][4][4], bf[2][4][4];
        ldB(ws, 0, bf[0]);
        ldA(as, 0, af[0]);
        #pragma unroll
        for (int ks = 0; ks < 4; ks++) {
            const int cur = ks & 1;
            if (ks < 3) {               // prefetch next k-step's fragments
                ldB(ws, ks + 1, bf[cur ^ 1]);
                ldA(as, ks + 1, af[cur ^ 1]);
            }
            #pragma unroll
            for (int i = 0; i < 4; i++)
                #pragma unroll
                for (int j = 0; j < 8; j++)
                    mma_f16(acc[i][j], af[cur][i], &bf[cur][j >> 1][(j & 1) * 2]);
        }
    };

    issue_next(); CP_COMMIT();
    issue_next(); CP_COMMIT();
    uint32_t co = 0;
    for (int kt = 0; kt < KT; kt++) {
        CP_WAIT1();
        __syncthreads();
        if (kt + 2 < KT) issue_next();
        CP_COMMIT();
        compute(co);
        co += STAGE_B; if (co == 3 * STAGE_B) co = 0;
    }
    CP_WAIT0();

    // -------- epilogue --------
    #pragma unroll
    for (int i = 0; i < 4; i++) {
        const int rowA = row0 + wr * 64 + i * 16 + g;
        float p0a, p1a, p0b, p1b;
        if (MODE == 0) {
            p0a = probs[2 * rowA + expert];
            p0b = probs[2 * (rowA + 8) + expert];
            p1a = p1b = 0.f;
        } else {
            p0a = probs[2 * rowA];       p1a = probs[2 * rowA + 1];
            p0b = probs[2 * (rowA + 8)]; p1b = probs[2 * (rowA + 8) + 1];
        }
        #pragma unroll
        for (int j = 0; j < 8; j++) {
            const int col = col0 + wn * 64 + j * 8 + c * 2;
            OutT* out0 = Csel + (size_t)rowA * Nfeat + col;
            OutT* out1 = Csel + (size_t)(rowA + 8) * Nfeat + col;
            if (MODE == 0) {
                const float b0 = bsel[col], b1 = bsel[col + 1];
                *(__half2*)out0 = __floats2half2_rn(p0a * gelu_exact(acc[i][j][0] + b0),
                                                    p0a * gelu_exact(acc[i][j][1] + b1));
                *(__half2*)out1 = __floats2half2_rn(p0b * gelu_exact(acc[i][j][2] + b0),
                                                    p0b * gelu_exact(acc[i][j][3] + b1));
            } else {
                const float bl0 = b0v[col], bl1 = b0v[col + 1];
                const float bh0 = b1v[col], bh1 = b1v[col + 1];
                out0[0] = acc[i][j][0] + p0a * bl0 + p1a * bh0;
                out0[1] = acc[i][j][1] + p0a * bl1 + p1a * bh1;
                out1[0] = acc[i][j][2] + p0b * bl0 + p1b * bh0;
                out1[1] = acc[i][j][3] + p0b * bl1 + p1b * bh1;
            }
        }
    }
}

// -------------------- launch --------------------
extern "C" void kernel_launch(void* const* d_in, const int* in_sizes, int n_in,
                              void* d_out, int out_size) {
    const float* x        = (const float*)d_in[0];
    const float* router_w = (const float*)d_in[1];
    const float* router_b = (const float*)d_in[2];
    const float* light_w1 = (const float*)d_in[3];
    const float* light_b1 = (const float*)d_in[4];
    const float* light_w2 = (const float*)d_in[5];
    const float* light_b2 = (const float*)d_in[6];
    const float* heavy_w1 = (const float*)d_in[7];
    const float* heavy_b1 = (const float*)d_in[8];
    const float* heavy_w2 = (const float*)d_in[9];
    const float* heavy_b2 = (const float*)d_in[10];
    float* out = (float*)d_out;

    __half *hl, *hh, *xh, *lw1h, *hw1h, *lw2h, *hw2h;
    float* probs;
    cudaGetSymbolAddress((void**)&hl, g_hl);
    cudaGetSymbolAddress((void**)&hh, g_hh);
    cudaGetSymbolAddress((void**)&xh, g_xh);
    cudaGetSymbolAddress((void**)&lw1h, g_lw1h);
    cudaGetSymbolAddress((void**)&hw1h, g_hw1h);
    cudaGetSymbolAddress((void**)&lw2h, g_lw2h);
    cudaGetSymbolAddress((void**)&hw2h, g_hw2h);
    cudaGetSymbolAddress((void**)&probs, g_probs);

    static bool attr_done = false;
    if (!attr_done) {
        cudaFuncSetAttribute((const void*)gemm_f16_kernel<0, __half>,
                             cudaFuncAttributeMaxDynamicSharedMemorySize, SMEM_BYTES);
        cudaFuncSetAttribute((const void*)gemm_f16_kernel<1, float>,
                             cudaFuncAttributeMaxDynamicSharedMemorySize, SMEM_BYTES);
        attr_done = true;
    }

    router_kernel<<<N_TOK / 8, 256>>>(x, router_w, router_b, probs, xh);

    {   // merged weight conversions
        const int n0 = LIGHT * HDIM / 4, n1 = HEAVY * HDIM / 4;
        const int n2 = HDIM * LIGHT / 4, n3 = HDIM * HEAVY / 4;
        const int total = n0 + n1 + n2 + n3;
        round16_all_kernel<<<(total + 255) / 256, 256>>>(
            light_w1, lw1h, n0, heavy_w1, hw1h, n1,
            light_w2, lw2h, n2, heavy_w2, hw2h, n3);
    }

    // merged fc1: cols [0,9) -> light (hl), cols [9,45) -> heavy (hh)
    {
        dim3 grid(LIGHT / 128 + HEAVY / 128, N_TOK / 128);
        gemm_f16_kernel<0, __half><<<grid, 128, SMEM_BYTES>>>(
            xh, lw1h, HDIM, nullptr, hw1h, HDIM, light_b1, heavy_b1,
            hl, hh, probs, LIGHT / 128);
    }
    // fc2 (dual segment): out = hl@lw2 + hh@hw2 + p0*b_l + p1*b_h
    {
        dim3 grid(HDIM / 128, N_TOK / 128);
        gemm_f16_kernel<1, float><<<grid, 128, SMEM_BYTES>>>(
            hl, lw2h, LIGHT, hh, hw2h, HEAVY, light_b2, heavy_b2,
            out, nullptr, probs, 0);
    }
}

// round 13
// speedup vs baseline: 1.1933x; 1.0348x over previous
#include <cuda_runtime.h>
#include <cuda_fp16.h>
#include <math.h>
#include <stdint.h>

// ---------------- problem constants ----------------
#define N_TOK 32768
#define HDIM  1152
#define LIGHT 1152
#define HEAVY 4608

// ---------------- static scratch (fp16 operands) ----------------
__device__ __half g_hl [(size_t)N_TOK * LIGHT];   // p0 * gelu(fc1_light)
__device__ __half g_hh [(size_t)N_TOK * HEAVY];   // p1 * gelu(fc1_heavy)
__device__ __half g_xh [(size_t)N_TOK * HDIM];
__device__ __half g_lw1h[(size_t)LIGHT * HDIM];
__device__ __half g_hw1h[(size_t)HEAVY * HDIM];
__device__ __half g_lw2h[(size_t)HDIM * LIGHT];
__device__ __half g_hw2h[(size_t)HDIM * HEAVY];
__device__ float  g_probs[2 * N_TOK];

__device__ __forceinline__ uint32_t smem_u32(const void* p) {
    uint32_t a;
    asm("{ .reg .u64 t; cvta.to.shared.u64 t, %1; cvt.u32.u64 %0, t; }" : "=r"(a) : "l"(p));
    return a;
}
__device__ __forceinline__ void cp_async16(uint32_t s, const void* g) {
    size_t gp = __cvta_generic_to_global(g);
    asm volatile("cp.async.cg.shared.global [%0], [%1], 16;" :: "r"(s), "l"(gp) : "memory");
}
#define CP_COMMIT() asm volatile("cp.async.commit_group;" ::: "memory")
#define CP_WAIT1()  asm volatile("cp.async.wait_group 1;" ::: "memory")
#define CP_WAIT0()  asm volatile("cp.async.wait_group 0;" ::: "memory")

__device__ __forceinline__ void ldmatrix_x4(uint32_t& r0, uint32_t& r1,
                                            uint32_t& r2, uint32_t& r3, uint32_t addr) {
    asm volatile("ldmatrix.sync.aligned.m8n8.x4.shared.b16 {%0,%1,%2,%3}, [%4];"
                 : "=r"(r0), "=r"(r1), "=r"(r2), "=r"(r3) : "r"(addr));
}
__device__ __forceinline__ void mma_f16(float* d, const uint32_t* a, const uint32_t* b) {
    asm volatile(
        "mma.sync.aligned.m16n8k16.row.col.f32.f16.f16.f32 "
        "{%0,%1,%2,%3}, {%4,%5,%6,%7}, {%8,%9}, {%0,%1,%2,%3};"
        : "+f"(d[0]), "+f"(d[1]), "+f"(d[2]), "+f"(d[3])
        : "r"(a[0]), "r"(a[1]), "r"(a[2]), "r"(a[3]), "r"(b[0]), "r"(b[1]));
}

__device__ __forceinline__ float gelu_exact(float v) {
    return 0.5f * v * (1.0f + erff(v * 0.70710678118654752f));
}

// -------------------- merged fp32 -> fp16 weight pre-round --------------------
__global__ void round16_all_kernel(const float* __restrict__ s0, __half* __restrict__ d0, int n0,
                                   const float* __restrict__ s1, __half* __restrict__ d1, int n1,
                                   const float* __restrict__ s2, __half* __restrict__ d2, int n2,
                                   const float* __restrict__ s3, __half* __restrict__ d3, int n3) {
    int i = blockIdx.x * blockDim.x + threadIdx.x;
    const float* s; __half* d;
    if (i < n0) { s = s0; d = d0; }
    else if ((i -= n0) < n1) { s = s1; d = d1; }
    else if ((i -= n1) < n2) { s = s2; d = d2; }
    else if ((i -= n2) < n3) { s = s3; d = d3; }
    else return;
    float4 v = ((const float4*)s)[i];
    ((__half2*)d)[2 * i]     = __floats2half2_rn(v.x, v.y);
    ((__half2*)d)[2 * i + 1] = __floats2half2_rn(v.z, v.w);
}

// -------------------- router (also converts x -> fp16) --------------------
__global__ void router_kernel(const float* __restrict__ x,
                              const float* __restrict__ rw,
                              const float* __restrict__ rb,
                              float* __restrict__ probs,
                              __half* __restrict__ xh) {
    int warp = (blockIdx.x * blockDim.x + threadIdx.x) >> 5;
    int lane = threadIdx.x & 31;
    if (warp >= N_TOK) return;
    const float* xp = x + (size_t)warp * HDIM;
    __half* xo = xh + (size_t)warp * HDIM;
    float a0 = 0.f, a1 = 0.f;
    #pragma unroll 4
    for (int h = lane; h < HDIM; h += 32) {
        float v = xp[h];
        xo[h] = __float2half_rn(v);
        a0 = fmaf(v, rw[h], a0);
        a1 = fmaf(v, rw[HDIM + h], a1);
    }
    #pragma unroll
    for (int off = 16; off; off >>= 1) {
        a0 += __shfl_xor_sync(0xffffffffu, a0, off);
        a1 += __shfl_xor_sync(0xffffffffu, a1, off);
    }
    if (lane == 0) {
        a0 += rb[0];
        a1 += rb[1];
        float m = fmaxf(a0, a1);
        float e0 = __expf(a0 - m), e1 = __expf(a1 - m);
        float inv = 1.0f / (e0 + e1);
        probs[2 * warp]     = e0 * inv;
        probs[2 * warp + 1] = e1 * inv;
    }
}

// -------------------- fp16 mma GEMM --------------------
// CTA 128x128, 128 threads, 4 warps (2x2), warp tile 64x64, BK=64,
// 3-stage cp.async, 96KB smem, 2 CTA/SM. Persistent global pointers.
// Deferred-tail pipelining: k-step 3's mma are issued at the TOP of the next
// iteration (before CP_WAIT/barrier/issue) so the tensor pipe drains under
// the chunk-boundary window.
// MODE 0 (merged fc1): blockIdx.x < ncol_light -> light expert, else heavy.
//        C[fp16] = probs[n,expert] * gelu(acc + bias[m]).
// MODE 1 (fc2): C[fp32] = acc(seg0) + acc(seg1) + p0*b0[m] + p1*b1[m].
#define STAGE_B 32768u
#define SMEM_BYTES (3 * 32768)

template <int MODE, typename OutT>
__global__ void __launch_bounds__(128, 2) gemm_f16_kernel(
    const __half* __restrict__ A0, const __half* __restrict__ W0, int K0,
    const __half* __restrict__ A1, const __half* __restrict__ W1, int K1,
    const float* __restrict__ b0v, const float* __restrict__ b1v,
    OutT* __restrict__ C, OutT* __restrict__ C2,
    const float* __restrict__ probs, int ncol_light)
{
    extern __shared__ char smc[];
    const uint32_t sbase = smem_u32(smc);
    const int tid  = threadIdx.x;
    const int wid  = tid >> 5, lane = tid & 31;
    const int wr   = wid >> 1;      // 0..1 : 64-row group
    const int wn   = wid & 1;       // 0..1 : 64-col group
    const int g    = lane >> 2;     // 0..7
    const int c    = lane & 3;      // 0..3
    const int row0 = blockIdx.y * 128;

    // ---- MODE 0: select expert by column-tile index
    const __half* Wsel = W0;
    const float*  bsel = b0v;
    OutT*         Csel = C;
    int           Nfeat, expert, colt;
    if (MODE == 0) {
        if ((int)blockIdx.x < ncol_light) {
            colt = blockIdx.x;              Nfeat = LIGHT; expert = 0;
        } else {
            colt = blockIdx.x - ncol_light; Nfeat = HEAVY; expert = 1;
            Wsel = W1; bsel = b1v; Csel = C2;
        }
    } else {
        colt = blockIdx.x; Nfeat = HDIM; expert = 0;
    }
    const int col0 = colt * 128;

    // ---- cp.async smem destination
    const int lrow = tid >> 3;      // 0..15
    const int ls   = tid & 7;       // 16B unit
    const uint32_t offR = (uint32_t)(lrow * 128 + ((ls ^ (lrow & 7)) * 16));

    // ---- persistent global source pointers
    const __half* pa = A0 + (size_t)(row0 + lrow) * K0 + ls * 8;
    const __half* pw = Wsel + (size_t)(col0 + lrow) * K0 + ls * 8;
    size_t rs = (size_t)16 * K0;

    // ---- ldmatrix lane components
    const int arow = wr * 64 + (lane & 15);
    const int asel = lane >> 4;
    const int nrow = wn * 64 + (lane & 7) + ((lane >> 4) << 3);
    const int bsel2 = (lane >> 3) & 1;

    float acc[4][8][4];
    #pragma unroll
    for (int i = 0; i < 4; i++)
        #pragma unroll
        for (int j = 0; j < 8; j++)
            #pragma unroll
            for (int q = 0; q < 4; q++) acc[i][j][q] = 0.f;

    const int KT0 = K0 >> 6;
    const int KT  = KT0 + ((MODE == 1) ? (K1 >> 6) : 0);

    int issued = 0;
    uint32_t so = 0;
    auto issue_next = [&]() {
        if (MODE == 1 && issued == KT0) {
            pa = A1 + (size_t)(row0 + lrow) * K1 + ls * 8;
            pw = W1 + (size_t)(col0 + lrow) * K1 + ls * 8;
            rs = (size_t)16 * K1;
        }
        #pragma unroll
        for (int i = 0; i < 8; i++) {
            cp_async16(sbase + so + offR + (uint32_t)i * 2048u,          pa + (size_t)i * rs);
            cp_async16(sbase + so + 16384u + offR + (uint32_t)i * 2048u, pw + (size_t)i * rs);
        }
        pa += 64; pw += 64;
        issued++;
        so += STAGE_B; if (so == 3 * STAGE_B) so = 0;
    };

    // fragment buffers (live across the chunk boundary for the deferred tail)
    uint32_t af[2][4][4], bf[2][4][4];

    auto ldA = [&](uint32_t as, int ks, uint32_t dst[4][4]) {
        const uint32_t p = (uint32_t)((((ks * 2 + asel) ^ (arow & 7)) * 16));
        const uint32_t base = as + (uint32_t)(arow * 128) + p;
        #pragma unroll
        for (int i = 0; i < 4; i++)
            ldmatrix_x4(dst[i][0], dst[i][1], dst[i][2], dst[i][3], base + (uint32_t)(i * 2048));
    };
    auto ldB = [&](uint32_t ws, int ks, uint32_t dst[4][4]) {
        const uint32_t p = (uint32_t)((((ks * 2 + bsel2) ^ (nrow & 7)) * 16));
        const uint32_t base = ws + (uint32_t)(nrow * 128) + p;
        #pragma unroll
        for (int j2 = 0; j2 < 4; j2++)
            ldmatrix_x4(dst[j2][0], dst[j2][1], dst[j2][2], dst[j2][3], base + (uint32_t)(j2 * 2048));
    };
    auto mma_block = [&](int buf) {
        #pragma unroll
        for (int i = 0; i < 4; i++)
            #pragma unroll
            for (int j = 0; j < 8; j++)
                mma_f16(acc[i][j], af[buf][i], &bf[buf][j >> 1][(j & 1) * 2]);
    };
    // k-steps 0..2 (+frag prefetch); leaves step-3 fragments in buf 1
    auto compute_head = [&](uint32_t co) {
        const uint32_t as = sbase + co;
        const uint32_t ws = as + 16384u;
        ldB(ws, 0, bf[0]);
        ldA(as, 0, af[0]);
        #pragma unroll
        for (int ks = 0; ks < 3; ks++) {
            const int cur = ks & 1;
            ldB(ws, ks + 1, bf[cur ^ 1]);
            ldA(as, ks + 1, af[cur ^ 1]);
            mma_block(cur);
        }
    };

    issue_next(); CP_COMMIT();
    issue_next(); CP_COMMIT();
    uint32_t co = 0;

    // prologue iteration (kt = 0)
    CP_WAIT1();
    __syncthreads();
    if (KT > 2) issue_next();
    CP_COMMIT();
    compute_head(co);
    co += STAGE_B; if (co == 3 * STAGE_B) co = 0;

    for (int kt = 1; kt < KT; kt++) {
        mma_block(1);               // deferred step-3 mma of previous chunk
        CP_WAIT1();
        __syncthreads();
        if (kt + 2 < KT) issue_next();
        CP_COMMIT();
        compute_head(co);
        co += STAGE_B; if (co == 3 * STAGE_B) co = 0;
    }
    mma_block(1);                   // final deferred tail
    CP_WAIT0();

    // -------- epilogue --------
    #pragma unroll
    for (int i = 0; i < 4; i++) {
        const int rowA = row0 + wr * 64 + i * 16 + g;
        float p0a, p1a, p0b, p1b;
        if (MODE == 0) {
            p0a = probs[2 * rowA + expert];
            p0b = probs[2 * (rowA + 8) + expert];
            p1a = p1b = 0.f;
        } else {
            p0a = probs[2 * rowA];       p1a = probs[2 * rowA + 1];
            p0b = probs[2 * (rowA + 8)]; p1b = probs[2 * (rowA + 8) + 1];
        }
        #pragma unroll
        for (int j = 0; j < 8; j++) {
            const int col = col0 + wn * 64 + j * 8 + c * 2;
            OutT* out0 = Csel + (size_t)rowA * Nfeat + col;
            OutT* out1 = Csel + (size_t)(rowA + 8) * Nfeat + col;
            if (MODE == 0) {
                const float b0 = bsel[col], b1 = bsel[col + 1];
                *(__half2*)out0 = __floats2half2_rn(p0a * gelu_exact(acc[i][j][0] + b0),
                                                    p0a * gelu_exact(acc[i][j][1] + b1));
                *(__half2*)out1 = __floats2half2_rn(p0b * gelu_exact(acc[i][j][2] + b0),
                                                    p0b * gelu_exact(acc[i][j][3] + b1));
            } else {
                const float bl0 = b0v[col], bl1 = b0v[col + 1];
                const float bh0 = b1v[col], bh1 = b1v[col + 1];
                out0[0] = acc[i][j][0] + p0a * bl0 + p1a * bh0;
                out0[1] = acc[i][j][1] + p0a * bl1 + p1a * bh1;
                out1[0] = acc[i][j][2] + p0b * bl0 + p1b * bh0;
                out1[1] = acc[i][j][3] + p0b * bl1 + p1b * bh1;
            }
        }
    }
}

// -------------------- launch --------------------
extern "C" void kernel_launch(void* const* d_in, const int* in_sizes, int n_in,
                              void* d_out, int out_size) {
    const float* x        = (const float*)d_in[0];
    const float* router_w = (const float*)d_in[1];
    const float* router_b = (const float*)d_in[2];
    const float* light_w1 = (const float*)d_in[3];
    const float* light_b1 = (const float*)d_in[4];
    const float* light_w2 = (const float*)d_in[5];
    const float* light_b2 = (const float*)d_in[6];
    const float* heavy_w1 = (const float*)d_in[7];
    const float* heavy_b1 = (const float*)d_in[8];
    const float* heavy_w2 = (const float*)d_in[9];
    const float* heavy_b2 = (const float*)d_in[10];
    float* out = (float*)d_out;

    __half *hl, *hh, *xh, *lw1h, *hw1h, *lw2h, *hw2h;
    float* probs;
    cudaGetSymbolAddress((void**)&hl, g_hl);
    cudaGetSymbolAddress((void**)&hh, g_hh);
    cudaGetSymbolAddress((void**)&xh, g_xh);
    cudaGetSymbolAddress((void**)&lw1h, g_lw1h);
    cudaGetSymbolAddress((void**)&hw1h, g_hw1h);
    cudaGetSymbolAddress((void**)&lw2h, g_lw2h);
    cudaGetSymbolAddress((void**)&hw2h, g_hw2h);
    cudaGetSymbolAddress((void**)&probs, g_probs);

    static bool attr_done = false;
    if (!attr_done) {
        cudaFuncSetAttribute((const void*)gemm_f16_kernel<0, __half>,
                             cudaFuncAttributeMaxDynamicSharedMemorySize, SMEM_BYTES);
        cudaFuncSetAttribute((const void*)gemm_f16_kernel<1, float>,
                             cudaFuncAttributeMaxDynamicSharedMemorySize, SMEM_BYTES);
        attr_done = true;
    }

    router_kernel<<<N_TOK / 8, 256>>>(x, router_w, router_b, probs, xh);

    {   // merged weight conversions
        const int n0 = LIGHT * HDIM / 4, n1 = HEAVY * HDIM / 4;
        const int n2 = HDIM * LIGHT / 4, n3 = HDIM * HEAVY / 4;
        const int total = n0 + n1 + n2 + n3;
        round16_all_kernel<<<(total + 255) / 256, 256>>>(
            light_w1, lw1h, n0, heavy_w1, hw1h, n1,
            light_w2, lw2h, n2, heavy_w2, hw2h, n3);
    }

    // merged fc1: cols [0,9) -> light (hl), cols [9,45) -> heavy (hh)
    {
        dim3 grid(LIGHT / 128 + HEAVY / 128, N_TOK / 128);
        gemm_f16_kernel<0, __half><<<grid, 128, SMEM_BYTES>>>(
            xh, lw1h, HDIM, nullptr, hw1h, HDIM, light_b1, heavy_b1,
            hl, hh, probs, LIGHT / 128);
    }
    // fc2 (dual segment): out = hl@lw2 + hh@hw2 + p0*b_l + p1*b_h
    {
        dim3 grid(HDIM / 128, N_TOK / 128);
        gemm_f16_kernel<1, float><<<grid, 128, SMEM_BYTES>>>(
            hl, lw2h, LIGHT, hh, hw2h, HEAVY, light_b2, heavy_b2,
            out, nullptr, probs, 0);
    }
}

// round 14
// speedup vs baseline: 1.2104x; 1.0144x over previous
#include <cuda_runtime.h>
#include <cuda_fp16.h>
#include <math.h>
#include <stdint.h>

// ---------------- problem constants ----------------
#define N_TOK 32768
#define HDIM  1152
#define LIGHT 1152
#define HEAVY 4608

// ---------------- static scratch (fp16 operands) ----------------
__device__ __half g_hl [(size_t)N_TOK * LIGHT];   // p0 * gelu(fc1_light)
__device__ __half g_hh [(size_t)N_TOK * HEAVY];   // p1 * gelu(fc1_heavy)
__device__ __half g_xh [(size_t)N_TOK * HDIM];
__device__ __half g_lw1h[(size_t)LIGHT * HDIM];
__device__ __half g_hw1h[(size_t)HEAVY * HDIM];
__device__ __half g_lw2h[(size_t)HDIM * LIGHT];
__device__ __half g_hw2h[(size_t)HDIM * HEAVY];
__device__ float  g_probs[2 * N_TOK];

__device__ __forceinline__ uint32_t smem_u32(const void* p) {
    uint32_t a;
    asm("{ .reg .u64 t; cvta.to.shared.u64 t, %1; cvt.u32.u64 %0, t; }" : "=r"(a) : "l"(p));
    return a;
}
__device__ __forceinline__ void cp_async16(uint32_t s, const void* g) {
    size_t gp = __cvta_generic_to_global(g);
    asm volatile("cp.async.cg.shared.global [%0], [%1], 16;" :: "r"(s), "l"(gp) : "memory");
}
#define CP_COMMIT() asm volatile("cp.async.commit_group;" ::: "memory")
#define CP_WAIT1()  asm volatile("cp.async.wait_group 1;" ::: "memory")
#define CP_WAIT0()  asm volatile("cp.async.wait_group 0;" ::: "memory")

__device__ __forceinline__ void ldmatrix_x4(uint32_t& r0, uint32_t& r1,
                                            uint32_t& r2, uint32_t& r3, uint32_t addr) {
    asm volatile("ldmatrix.sync.aligned.m8n8.x4.shared.b16 {%0,%1,%2,%3}, [%4];"
                 : "=r"(r0), "=r"(r1), "=r"(r2), "=r"(r3) : "r"(addr));
}
__device__ __forceinline__ void mma_f16(float* d, const uint32_t* a, const uint32_t* b) {
    asm volatile(
        "mma.sync.aligned.m16n8k16.row.col.f32.f16.f16.f32 "
        "{%0,%1,%2,%3}, {%4,%5,%6,%7}, {%8,%9}, {%0,%1,%2,%3};"
        : "+f"(d[0]), "+f"(d[1]), "+f"(d[2]), "+f"(d[3])
        : "r"(a[0]), "r"(a[1]), "r"(a[2]), "r"(a[3]), "r"(b[0]), "r"(b[1]));
}

__device__ __forceinline__ float gelu_exact(float v) {
    return 0.5f * v * (1.0f + erff(v * 0.70710678118654752f));
}

// -------------------- merged prologue: router + all weight conversions ----
// blocks [0, N_TOK/8): one warp per token -> probs + xh
// blocks >= N_TOK/8:   fp32 -> fp16 weight conversion (4 regions)
__global__ void prologue_kernel(const float* __restrict__ x,
                                const float* __restrict__ rw,
                                const float* __restrict__ rb,
                                float* __restrict__ probs,
                                __half* __restrict__ xh,
                                const float* __restrict__ s0, __half* __restrict__ d0, int n0,
                                const float* __restrict__ s1, __half* __restrict__ d1, int n1,
                                const float* __restrict__ s2, __half* __restrict__ d2, int n2,
                                const float* __restrict__ s3, __half* __restrict__ d3, int n3) {
    const int ROUTER_BLOCKS = N_TOK / 8;
    if ((int)blockIdx.x >= ROUTER_BLOCKS) {
        int i = ((int)blockIdx.x - ROUTER_BLOCKS) * 256 + threadIdx.x;
        const float* s; __half* d;
        if (i < n0) { s = s0; d = d0; }
        else if ((i -= n0) < n1) { s = s1; d = d1; }
        else if ((i -= n1) < n2) { s = s2; d = d2; }
        else if ((i -= n2) < n3) { s = s3; d = d3; }
        else return;
        float4 v = ((const float4*)s)[i];
        ((__half2*)d)[2 * i]     = __floats2half2_rn(v.x, v.y);
        ((__half2*)d)[2 * i + 1] = __floats2half2_rn(v.z, v.w);
        return;
    }
    int warp = (blockIdx.x * blockDim.x + threadIdx.x) >> 5;
    int lane = threadIdx.x & 31;
    const float* xp = x + (size_t)warp * HDIM;
    __half* xo = xh + (size_t)warp * HDIM;
    float a0 = 0.f, a1 = 0.f;
    #pragma unroll 4
    for (int h = lane; h < HDIM; h += 32) {
        float v = xp[h];
        xo[h] = __float2half_rn(v);
        a0 = fmaf(v, rw[h], a0);
        a1 = fmaf(v, rw[HDIM + h], a1);
    }
    #pragma unroll
    for (int off = 16; off; off >>= 1) {
        a0 += __shfl_xor_sync(0xffffffffu, a0, off);
        a1 += __shfl_xor_sync(0xffffffffu, a1, off);
    }
    if (lane == 0) {
        a0 += rb[0];
        a1 += rb[1];
        float m = fmaxf(a0, a1);
        float e0 = __expf(a0 - m), e1 = __expf(a1 - m);
        float inv = 1.0f / (e0 + e1);
        probs[2 * warp]     = e0 * inv;
        probs[2 * warp + 1] = e1 * inv;
    }
}

// -------------------- fp16 mma GEMM --------------------
// CTA 128x128, 128 threads, 4 warps (2x2), warp tile 64x64, BK=64,
// 3-stage cp.async, 96KB smem, 2 CTA/SM. Persistent global pointers.
// Deferred-tail pipelining + co-resident CTA phase-stagger.
// MODE 0 (merged fc1): blockIdx.x < ncol_light -> light expert, else heavy.
//        C[fp16] = probs[n,expert] * gelu(acc + bias[m]).
// MODE 1 (fc2): C[fp32] = acc(seg0) + acc(seg1) + p0*b0[m] + p1*b1[m].
#define STAGE_B 32768u
#define SMEM_BYTES (3 * 32768)

template <int MODE, typename OutT>
__global__ void __launch_bounds__(128, 2) gemm_f16_kernel(
    const __half* __restrict__ A0, const __half* __restrict__ W0, int K0,
    const __half* __restrict__ A1, const __half* __restrict__ W1, int K1,
    const float* __restrict__ b0v, const float* __restrict__ b1v,
    OutT* __restrict__ C, OutT* __restrict__ C2,
    const float* __restrict__ probs, int ncol_light)
{
    extern __shared__ char smc[];
    const uint32_t sbase = smem_u32(smc);
    const int tid  = threadIdx.x;
    const int wid  = tid >> 5, lane = tid & 31;
    const int wr   = wid >> 1;      // 0..1 : 64-row group
    const int wn   = wid & 1;       // 0..1 : 64-col group
    const int g    = lane >> 2;     // 0..7
    const int c    = lane & 3;      // 0..3
    const int row0 = blockIdx.y * 128;

    // ---- phase-stagger: antiphase the two co-resident CTAs per SM.
    // Classic placement maps bid and bid+148 to the same SM; (bid/148)&1
    // separates them in wave 1, and the offset self-perpetuates.
    {
        const int bid = (int)(blockIdx.y * gridDim.x + blockIdx.x);
        if ((bid / 148) & 1) {
            unsigned long long t0 = clock64();
            while (clock64() - t0 < 2500ull) {}
        }
    }

    // ---- MODE 0: select expert by column-tile index
    const __half* Wsel = W0;
    const float*  bsel = b0v;
    OutT*         Csel = C;
    int           Nfeat, expert, colt;
    if (MODE == 0) {
        if ((int)blockIdx.x < ncol_light) {
            colt = blockIdx.x;              Nfeat = LIGHT; expert = 0;
        } else {
            colt = blockIdx.x - ncol_light; Nfeat = HEAVY; expert = 1;
            Wsel = W1; bsel = b1v; Csel = C2;
        }
    } else {
        colt = blockIdx.x; Nfeat = HDIM; expert = 0;
    }
    const int col0 = colt * 128;

    // ---- cp.async smem destination
    const int lrow = tid >> 3;      // 0..15
    const int ls   = tid & 7;       // 16B unit
    const uint32_t offR = (uint32_t)(lrow * 128 + ((ls ^ (lrow & 7)) * 16));

    // ---- persistent global source pointers
    const __half* pa = A0 + (size_t)(row0 + lrow) * K0 + ls * 8;
    const __half* pw = Wsel + (size_t)(col0 + lrow) * K0 + ls * 8;
    size_t rs = (size_t)16 * K0;

    // ---- ldmatrix lane components
    const int arow = wr * 64 + (lane & 15);
    const int asel = lane >> 4;
    const int nrow = wn * 64 + (lane & 7) + ((lane >> 4) << 3);
    const int bsel2 = (lane >> 3) & 1;

    float acc[4][8][4];
    #pragma unroll
    for (int i = 0; i < 4; i++)
        #pragma unroll
        for (int j = 0; j < 8; j++)
            #pragma unroll
            for (int q = 0; q < 4; q++) acc[i][j][q] = 0.f;

    const int KT0 = K0 >> 6;
    const int KT  = KT0 + ((MODE == 1) ? (K1 >> 6) : 0);

    int issued = 0;
    uint32_t so = 0;
    auto issue_next = [&]() {
        if (MODE == 1 && issued == KT0) {
            pa = A1 + (size_t)(row0 + lrow) * K1 + ls * 8;
            pw = W1 + (size_t)(col0 + lrow) * K1 + ls * 8;
            rs = (size_t)16 * K1;
        }
        #pragma unroll
        for (int i = 0; i < 8; i++) {
            cp_async16(sbase + so + offR + (uint32_t)i * 2048u,          pa + (size_t)i * rs);
            cp_async16(sbase + so + 16384u + offR + (uint32_t)i * 2048u, pw + (size_t)i * rs);
        }
        pa += 64; pw += 64;
        issued++;
        so += STAGE_B; if (so == 3 * STAGE_B) so = 0;
    };

    // fragment buffers (live across the chunk boundary for the deferred tail)
    uint32_t af[2][4][4], bf[2][4][4];

    auto ldA = [&](uint32_t as, int ks, uint32_t dst[4][4]) {
        const uint32_t p = (uint32_t)((((ks * 2 + asel) ^ (arow & 7)) * 16));
        const uint32_t base = as + (uint32_t)(arow * 128) + p;
        #pragma unroll
        for (int i = 0; i < 4; i++)
            ldmatrix_x4(dst[i][0], dst[i][1], dst[i][2], dst[i][3], base + (uint32_t)(i * 2048));
    };
    auto ldB = [&](uint32_t ws, int ks, uint32_t dst[4][4]) {
        const uint32_t p = (uint32_t)((((ks * 2 + bsel2) ^ (nrow & 7)) * 16));
        const uint32_t base = ws + (uint32_t)(nrow * 128) + p;
        #pragma unroll
        for (int j2 = 0; j2 < 4; j2++)
            ldmatrix_x4(dst[j2][0], dst[j2][1], dst[j2][2], dst[j2][3], base + (uint32_t)(j2 * 2048));
    };
    auto mma_block = [&](int buf) {
        #pragma unroll
        for (int i = 0; i < 4; i++)
            #pragma unroll
            for (int j = 0; j < 8; j++)
                mma_f16(acc[i][j], af[buf][i], &bf[buf][j >> 1][(j & 1) * 2]);
    };
    // k-steps 0..2 (+frag prefetch); leaves step-3 fragments in buf 1
    auto compute_head = [&](uint32_t co) {
        const uint32_t as = sbase + co;
        const uint32_t ws = as + 16384u;
        ldB(ws, 0, bf[0]);
        ldA(as, 0, af[0]);
        #pragma unroll
        for (int ks = 0; ks < 3; ks++) {
            const int cur = ks & 1;
            ldB(ws, ks + 1, bf[cur ^ 1]);
            ldA(as, ks + 1, af[cur ^ 1]);
            mma_block(cur);
        }
    };

    issue_next(); CP_COMMIT();
    issue_next(); CP_COMMIT();
    uint32_t co = 0;

    // prologue iteration (kt = 0)
    CP_WAIT1();
    __syncthreads();
    if (KT > 2) issue_next();
    CP_COMMIT();
    compute_head(co);
    co += STAGE_B; if (co == 3 * STAGE_B) co = 0;

    for (int kt = 1; kt < KT; kt++) {
        mma_block(1);               // deferred step-3 mma of previous chunk
        CP_WAIT1();
        __syncthreads();
        if (kt + 2 < KT) issue_next();
        CP_COMMIT();
        compute_head(co);
        co += STAGE_B; if (co == 3 * STAGE_B) co = 0;
    }
    mma_block(1);                   // final deferred tail
    CP_WAIT0();

    // -------- epilogue --------
    #pragma unroll
    for (int i = 0; i < 4; i++) {
        const int rowA = row0 + wr * 64 + i * 16 + g;
        float p0a, p1a, p0b, p1b;
        if (MODE == 0) {
            p0a = probs[2 * rowA + expert];
            p0b = probs[2 * (rowA + 8) + expert];
            p1a = p1b = 0.f;
        } else {
            p0a = probs[2 * rowA];       p1a = probs[2 * rowA + 1];
            p0b = probs[2 * (rowA + 8)]; p1b = probs[2 * (rowA + 8) + 1];
        }
        #pragma unroll
        for (int j = 0; j < 8; j++) {
            const int col = col0 + wn * 64 + j * 8 + c * 2;
            OutT* out0 = Csel + (size_t)rowA * Nfeat + col;
            OutT* out1 = Csel + (size_t)(rowA + 8) * Nfeat + col;
            if (MODE == 0) {
                const float b0 = bsel[col], b1 = bsel[col + 1];
                *(__half2*)out0 = __floats2half2_rn(p0a * gelu_exact(acc[i][j][0] + b0),
                                                    p0a * gelu_exact(acc[i][j][1] + b1));
                *(__half2*)out1 = __floats2half2_rn(p0b * gelu_exact(acc[i][j][2] + b0),
                                                    p0b * gelu_exact(acc[i][j][3] + b1));
            } else {
                const float bl0 = b0v[col], bl1 = b0v[col + 1];
                const float bh0 = b1v[col], bh1 = b1v[col + 1];
                out0[0] = acc[i][j][0] + p0a * bl0 + p1a * bh0;
                out0[1] = acc[i][j][1] + p0a * bl1 + p1a * bh1;
                out1[0] = acc[i][j][2] + p0b * bl0 + p1b * bh0;
                out1[1] = acc[i][j][3] + p0b * bl1 + p1b * bh1;
            }
        }
    }
}

// -------------------- launch --------------------
extern "C" void kernel_launch(void* const* d_in, const int* in_sizes, int n_in,
                              void* d_out, int out_size) {
    const float* x        = (const float*)d_in[0];
    const float* router_w = (const float*)d_in[1];
    const float* router_b = (const float*)d_in[2];
    const float* light_w1 = (const float*)d_in[3];
    const float* light_b1 = (const float*)d_in[4];
    const float* light_w2 = (const float*)d_in[5];
    const float* light_b2 = (const float*)d_in[6];
    const float* heavy_w1 = (const float*)d_in[7];
    const float* heavy_b1 = (const float*)d_in[8];
    const float* heavy_w2 = (const float*)d_in[9];
    const float* heavy_b2 = (const float*)d_in[10];
    float* out = (float*)d_out;

    __half *hl, *hh, *xh, *lw1h, *hw1h, *lw2h, *hw2h;
    float* probs;
    cudaGetSymbolAddress((void**)&hl, g_hl);
    cudaGetSymbolAddress((void**)&hh, g_hh);
    cudaGetSymbolAddress((void**)&xh, g_xh);
    cudaGetSymbolAddress((void**)&lw1h, g_lw1h);
    cudaGetSymbolAddress((void**)&hw1h, g_hw1h);
    cudaGetSymbolAddress((void**)&lw2h, g_lw2h);
    cudaGetSymbolAddress((void**)&hw2h, g_hw2h);
    cudaGetSymbolAddress((void**)&probs, g_probs);

    static bool attr_done = false;
    if (!attr_done) {
        cudaFuncSetAttribute((const void*)gemm_f16_kernel<0, __half>,
                             cudaFuncAttributeMaxDynamicSharedMemorySize, SMEM_BYTES);
        cudaFuncSetAttribute((const void*)gemm_f16_kernel<1, float>,
                             cudaFuncAttributeMaxDynamicSharedMemorySize, SMEM_BYTES);
        attr_done = true;
    }

    // merged prologue: router (4096 blocks) + weight conversion
    {
        const int n0 = LIGHT * HDIM / 4, n1 = HEAVY * HDIM / 4;
        const int n2 = HDIM * LIGHT / 4, n3 = HDIM * HEAVY / 4;
        const int wblocks = (n0 + n1 + n2 + n3 + 255) / 256;
        prologue_kernel<<<N_TOK / 8 + wblocks, 256>>>(
            x, router_w, router_b, probs, xh,
            light_w1, lw1h, n0, heavy_w1, hw1h, n1,
            light_w2, lw2h, n2, heavy_w2, hw2h, n3);
    }

    // merged fc1: cols [0,9) -> light (hl), cols [9,45) -> heavy (hh)
    {
        dim3 grid(LIGHT / 128 + HEAVY / 128, N_TOK / 128);
        gemm_f16_kernel<0, __half><<<grid, 128, SMEM_BYTES>>>(
            xh, lw1h, HDIM, nullptr, hw1h, HDIM, light_b1, heavy_b1,
            hl, hh, probs, LIGHT / 128);
    }
    // fc2 (dual segment): out = hl@lw2 + hh@hw2 + p0*b_l + p1*b_h
    {
        dim3 grid(HDIM / 128, N_TOK / 128);
        gemm_f16_kernel<1, float><<<grid, 128, SMEM_BYTES>>>(
            hl, lw2h, LIGHT, hh, hw2h, HEAVY, light_b2, heavy_b2,
            out, nullptr, probs, 0);
    }
}

// round 15
// speedup vs baseline: 1.2730x; 1.0517x over previous
#include <cuda_runtime.h>
#include <cuda_fp16.h>
#include <math.h>
#include <stdint.h>

// ---------------- problem constants ----------------
#define N_TOK 32768
#define HDIM  1152
#define LIGHT 1152
#define HEAVY 4608

// ---------------- static scratch (fp16 operands) ----------------
__device__ __half g_hl [(size_t)N_TOK * LIGHT];   // p0 * gelu(fc1_light)
__device__ __half g_hh [(size_t)N_TOK * HEAVY];   // p1 * gelu(fc1_heavy)
__device__ __half g_xh [(size_t)N_TOK * HDIM];
__device__ __half g_lw1h[(size_t)LIGHT * HDIM];
__device__ __half g_hw1h[(size_t)HEAVY * HDIM];
__device__ __half g_lw2h[(size_t)HDIM * LIGHT];
__device__ __half g_hw2h[(size_t)HDIM * HEAVY];
__device__ float  g_probs[2 * N_TOK];

__device__ __forceinline__ uint32_t smem_u32(const void* p) {
    uint32_t a;
    asm("{ .reg .u64 t; cvta.to.shared.u64 t, %1; cvt.u32.u64 %0, t; }" : "=r"(a) : "l"(p));
    return a;
}
__device__ __forceinline__ void cp_async16(uint32_t s, const void* g) {
    size_t gp = __cvta_generic_to_global(g);
    asm volatile("cp.async.cg.shared.global [%0], [%1], 16;" :: "r"(s), "l"(gp) : "memory");
}
#define CP_COMMIT() asm volatile("cp.async.commit_group;" ::: "memory")
#define CP_WAIT1()  asm volatile("cp.async.wait_group 1;" ::: "memory")
#define CP_WAIT0()  asm volatile("cp.async.wait_group 0;" ::: "memory")

__device__ __forceinline__ void ldmatrix_x4(uint32_t& r0, uint32_t& r1,
                                            uint32_t& r2, uint32_t& r3, uint32_t addr) {
    asm volatile("ldmatrix.sync.aligned.m8n8.x4.shared.b16 {%0,%1,%2,%3}, [%4];"
                 : "=r"(r0), "=r"(r1), "=r"(r2), "=r"(r3) : "r"(addr));
}
__device__ __forceinline__ void mma_f16(float* d, const uint32_t* a, const uint32_t* b) {
    asm volatile(
        "mma.sync.aligned.m16n8k16.row.col.f32.f16.f16.f32 "
        "{%0,%1,%2,%3}, {%4,%5,%6,%7}, {%8,%9}, {%0,%1,%2,%3};"
        : "+f"(d[0]), "+f"(d[1]), "+f"(d[2]), "+f"(d[3])
        : "r"(a[0]), "r"(a[1]), "r"(a[2]), "r"(a[3]), "r"(b[0]), "r"(b[1]));
}

// fast GELU: tanh form with HW tanh.approx.f32 (sm_75+)
__device__ __forceinline__ float gelu_fast(float v) {
    float u = 0.7978845608028654f * fmaf(0.044715f * v, v * v, v);
    float t;
    asm("tanh.approx.f32 %0, %1;" : "=f"(t) : "f"(u));
    return 0.5f * v * (1.0f + t);
}

// -------------------- merged prologue: router + all weight conversions ----
// blocks [0, N_TOK/8): one warp per token -> probs + xh
// blocks >= N_TOK/8:   fp32 -> fp16 weight conversion (4 regions)
__global__ void prologue_kernel(const float* __restrict__ x,
                                const float* __restrict__ rw,
                                const float* __restrict__ rb,
                                float* __restrict__ probs,
                                __half* __restrict__ xh,
                                const float* __restrict__ s0, __half* __restrict__ d0, int n0,
                                const float* __restrict__ s1, __half* __restrict__ d1, int n1,
                                const float* __restrict__ s2, __half* __restrict__ d2, int n2,
                                const float* __restrict__ s3, __half* __restrict__ d3, int n3) {
    const int ROUTER_BLOCKS = N_TOK / 8;
    if ((int)blockIdx.x >= ROUTER_BLOCKS) {
        int i = ((int)blockIdx.x - ROUTER_BLOCKS) * 256 + threadIdx.x;
        const float* s; __half* d;
        if (i < n0) { s = s0; d = d0; }
        else if ((i -= n0) < n1) { s = s1; d = d1; }
        else if ((i -= n1) < n2) { s = s2; d = d2; }
        else if ((i -= n2) < n3) { s = s3; d = d3; }
        else return;
        float4 v = ((const float4*)s)[i];
        ((__half2*)d)[2 * i]     = __floats2half2_rn(v.x, v.y);
        ((__half2*)d)[2 * i + 1] = __floats2half2_rn(v.z, v.w);
        return;
    }
    int warp = (blockIdx.x * blockDim.x + threadIdx.x) >> 5;
    int lane = threadIdx.x & 31;
    const float* xp = x + (size_t)warp * HDIM;
    __half* xo = xh + (size_t)warp * HDIM;
    float a0 = 0.f, a1 = 0.f;
    #pragma unroll 4
    for (int h = lane; h < HDIM; h += 32) {
        float v = xp[h];
        xo[h] = __float2half_rn(v);
        a0 = fmaf(v, rw[h], a0);
        a1 = fmaf(v, rw[HDIM + h], a1);
    }
    #pragma unroll
    for (int off = 16; off; off >>= 1) {
        a0 += __shfl_xor_sync(0xffffffffu, a0, off);
        a1 += __shfl_xor_sync(0xffffffffu, a1, off);
    }
    if (lane == 0) {
        a0 += rb[0];
        a1 += rb[1];
        float m = fmaxf(a0, a1);
        float e0 = __expf(a0 - m), e1 = __expf(a1 - m);
        float inv = 1.0f / (e0 + e1);
        probs[2 * warp]     = e0 * inv;
        probs[2 * warp + 1] = e1 * inv;
    }
}

// -------------------- fp16 mma GEMM --------------------
// CTA 128x128, 128 threads, 4 warps (2x2), warp tile 64x64, BK=64,
// 3-stage cp.async, 96KB smem, 2 CTA/SM. Persistent global pointers.
// Deferred-tail pipelining + co-resident CTA phase-stagger.
// MODE 0 (merged fc1): blockIdx.x < ncol_light -> light expert, else heavy.
//        C[fp16] = probs[n,expert] * gelu(acc + bias[m]).
// MODE 1 (fc2): C[fp32] = acc(seg0) + acc(seg1) + p0*b0[m] + p1*b1[m].
#define STAGE_B 32768u
#define SMEM_BYTES (3 * 32768)

template <int MODE, typename OutT>
__global__ void __launch_bounds__(128, 2) gemm_f16_kernel(
    const __half* __restrict__ A0, const __half* __restrict__ W0, int K0,
    const __half* __restrict__ A1, const __half* __restrict__ W1, int K1,
    const float* __restrict__ b0v, const float* __restrict__ b1v,
    OutT* __restrict__ C, OutT* __restrict__ C2,
    const float* __restrict__ probs, int ncol_light)
{
    extern __shared__ char smc[];
    const uint32_t sbase = smem_u32(smc);
    const int tid  = threadIdx.x;
    const int wid  = tid >> 5, lane = tid & 31;
    const int wr   = wid >> 1;      // 0..1 : 64-row group
    const int wn   = wid & 1;       // 0..1 : 64-col group
    const int g    = lane >> 2;     // 0..7
    const int c    = lane & 3;      // 0..3
    const int row0 = blockIdx.y * 128;

    // ---- phase-stagger: antiphase the two co-resident CTAs per SM.
    {
        const int bid = (int)(blockIdx.y * gridDim.x + blockIdx.x);
        if ((bid / 148) & 1) {
            unsigned long long t0 = clock64();
            while (clock64() - t0 < 2500ull) {}
        }
    }

    // ---- MODE 0: select expert by column-tile index
    const __half* Wsel = W0;
    const float*  bsel = b0v;
    OutT*         Csel = C;
    int           Nfeat, expert, colt;
    if (MODE == 0) {
        if ((int)blockIdx.x < ncol_light) {
            colt = blockIdx.x;              Nfeat = LIGHT; expert = 0;
        } else {
            colt = blockIdx.x - ncol_light; Nfeat = HEAVY; expert = 1;
            Wsel = W1; bsel = b1v; Csel = C2;
        }
    } else {
        colt = blockIdx.x; Nfeat = HDIM; expert = 0;
    }
    const int col0 = colt * 128;

    // ---- cp.async smem destination
    const int lrow = tid >> 3;      // 0..15
    const int ls   = tid & 7;       // 16B unit
    const uint32_t offR = (uint32_t)(lrow * 128 + ((ls ^ (lrow & 7)) * 16));

    // ---- persistent global source pointers
    const __half* pa = A0 + (size_t)(row0 + lrow) * K0 + ls * 8;
    const __half* pw = Wsel + (size_t)(col0 + lrow) * K0 + ls * 8;
    size_t rs = (size_t)16 * K0;

    // ---- ldmatrix lane components
    const int arow = wr * 64 + (lane & 15);
    const int asel = lane >> 4;
    const int nrow = wn * 64 + (lane & 7) + ((lane >> 4) << 3);
    const int bsel2 = (lane >> 3) & 1;

    float acc[4][8][4];
    #pragma unroll
    for (int i = 0; i < 4; i++)
        #pragma unroll
        for (int j = 0; j < 8; j++)
            #pragma unroll
            for (int q = 0; q < 4; q++) acc[i][j][q] = 0.f;

    const int KT0 = K0 >> 6;
    const int KT  = KT0 + ((MODE == 1) ? (K1 >> 6) : 0);

    int issued = 0;
    uint32_t so = 0;
    auto issue_next = [&]() {
        if (MODE == 1 && issued == KT0) {
            pa = A1 + (size_t)(row0 + lrow) * K1 + ls * 8;
            pw = W1 + (size_t)(col0 + lrow) * K1 + ls * 8;
            rs = (size_t)16 * K1;
        }
        #pragma unroll
        for (int i = 0; i < 8; i++) {
            cp_async16(sbase + so + offR + (uint32_t)i * 2048u,          pa + (size_t)i * rs);
            cp_async16(sbase + so + 16384u + offR + (uint32_t)i * 2048u, pw + (size_t)i * rs);
        }
        pa += 64; pw += 64;
        issued++;
        so += STAGE_B; if (so == 3 * STAGE_B) so = 0;
    };

    // fragment buffers (live across the chunk boundary for the deferred tail)
    uint32_t af[2][4][4], bf[2][4][4];

    auto ldA = [&](uint32_t as, int ks, uint32_t dst[4][4]) {
        const uint32_t p = (uint32_t)((((ks * 2 + asel) ^ (arow & 7)) * 16));
        const uint32_t base = as + (uint32_t)(arow * 128) + p;
        #pragma unroll
        for (int i = 0; i < 4; i++)
            ldmatrix_x4(dst[i][0], dst[i][1], dst[i][2], dst[i][3], base + (uint32_t)(i * 2048));
    };
    auto ldB = [&](uint32_t ws, int ks, uint32_t dst[4][4]) {
        const uint32_t p = (uint32_t)((((ks * 2 + bsel2) ^ (nrow & 7)) * 16));
        const uint32_t base = ws + (uint32_t)(nrow * 128) + p;
        #pragma unroll
        for (int j2 = 0; j2 < 4; j2++)
            ldmatrix_x4(dst[j2][0], dst[j2][1], dst[j2][2], dst[j2][3], base + (uint32_t)(j2 * 2048));
    };
    auto mma_block = [&](int buf) {
        #pragma unroll
        for (int i = 0; i < 4; i++)
            #pragma unroll
            for (int j = 0; j < 8; j++)
                mma_f16(acc[i][j], af[buf][i], &bf[buf][j >> 1][(j & 1) * 2]);
    };
    // k-steps 0..2 (+frag prefetch); leaves step-3 fragments in buf 1
    auto compute_head = [&](uint32_t co) {
        const uint32_t as = sbase + co;
        const uint32_t ws = as + 16384u;
        ldB(ws, 0, bf[0]);
        ldA(as, 0, af[0]);
        #pragma unroll
        for (int ks = 0; ks < 3; ks++) {
            const int cur = ks & 1;
            ldB(ws, ks + 1, bf[cur ^ 1]);
            ldA(as, ks + 1, af[cur ^ 1]);
            mma_block(cur);
        }
    };

    issue_next(); CP_COMMIT();
    issue_next(); CP_COMMIT();
    uint32_t co = 0;

    // prologue iteration (kt = 0)
    CP_WAIT1();
    __syncthreads();
    if (KT > 2) issue_next();
    CP_COMMIT();
    compute_head(co);
    co += STAGE_B; if (co == 3 * STAGE_B) co = 0;

    for (int kt = 1; kt < KT; kt++) {
        mma_block(1);               // deferred step-3 mma of previous chunk
        CP_WAIT1();
        __syncthreads();
        if (kt + 2 < KT) issue_next();
        CP_COMMIT();
        compute_head(co);
        co += STAGE_B; if (co == 3 * STAGE_B) co = 0;
    }
    mma_block(1);                   // final deferred tail
    CP_WAIT0();

    // -------- epilogue --------
    #pragma unroll
    for (int i = 0; i < 4; i++) {
        const int rowA = row0 + wr * 64 + i * 16 + g;
        float p0a, p1a, p0b, p1b;
        if (MODE == 0) {
            p0a = probs[2 * rowA + expert];
            p0b = probs[2 * (rowA + 8) + expert];
            p1a = p1b = 0.f;
        } else {
            p0a = probs[2 * rowA];       p1a = probs[2 * rowA + 1];
            p0b = probs[2 * (rowA + 8)]; p1b = probs[2 * (rowA + 8) + 1];
        }
        #pragma unroll
        for (int j = 0; j < 8; j++) {
            const int col = col0 + wn * 64 + j * 8 + c * 2;
            OutT* out0 = Csel + (size_t)rowA * Nfeat + col;
            OutT* out1 = Csel + (size_t)(rowA + 8) * Nfeat + col;
            if (MODE == 0) {
                const float b0 = bsel[col], b1 = bsel[col + 1];
                *(__half2*)out0 = __floats2half2_rn(p0a * gelu_fast(acc[i][j][0] + b0),
                                                    p0a * gelu_fast(acc[i][j][1] + b1));
                *(__half2*)out1 = __floats2half2_rn(p0b * gelu_fast(acc[i][j][2] + b0),
                                                    p0b * gelu_fast(acc[i][j][3] + b1));
            } else {
                const float bl0 = b0v[col], bl1 = b0v[col + 1];
                const float bh0 = b1v[col], bh1 = b1v[col + 1];
                out0[0] = acc[i][j][0] + p0a * bl0 + p1a * bh0;
                out0[1] = acc[i][j][1] + p0a * bl1 + p1a * bh1;
                out1[0] = acc[i][j][2] + p0b * bl0 + p1b * bh0;
                out1[1] = acc[i][j][3] + p0b * bl1 + p1b * bh1;
            }
        }
    }
}

// -------------------- launch --------------------
extern "C" void kernel_launch(void* const* d_in, const int* in_sizes, int n_in,
                              void* d_out, int out_size) {
    const float* x        = (const float*)d_in[0];
    const float* router_w = (const float*)d_in[1];
    const float* router_b = (const float*)d_in[2];
    const float* light_w1 = (const float*)d_in[3];
    const float* light_b1 = (const float*)d_in[4];
    const float* light_w2 = (const float*)d_in[5];
    const float* light_b2 = (const float*)d_in[6];
    const float* heavy_w1 = (const float*)d_in[7];
    const float* heavy_b1 = (const float*)d_in[8];
    const float* heavy_w2 = (const float*)d_in[9];
    const float* heavy_b2 = (const float*)d_in[10];
    float* out = (float*)d_out;

    __half *hl, *hh, *xh, *lw1h, *hw1h, *lw2h, *hw2h;
    float* probs;
    cudaGetSymbolAddress((void**)&hl, g_hl);
    cudaGetSymbolAddress((void**)&hh, g_hh);
    cudaGetSymbolAddress((void**)&xh, g_xh);
    cudaGetSymbolAddress((void**)&lw1h, g_lw1h);
    cudaGetSymbolAddress((void**)&hw1h, g_hw1h);
    cudaGetSymbolAddress((void**)&lw2h, g_lw2h);
    cudaGetSymbolAddress((void**)&hw2h, g_hw2h);
    cudaGetSymbolAddress((void**)&probs, g_probs);

    static bool attr_done = false;
    if (!attr_done) {
        cudaFuncSetAttribute((const void*)gemm_f16_kernel<0, __half>,
                             cudaFuncAttributeMaxDynamicSharedMemorySize, SMEM_BYTES);
        cudaFuncSetAttribute((const void*)gemm_f16_kernel<1, float>,
                             cudaFuncAttributeMaxDynamicSharedMemorySize, SMEM_BYTES);
        attr_done = true;
    }

    // merged prologue: router (4096 blocks) + weight conversion
    {
        const int n0 = LIGHT * HDIM / 4, n1 = HEAVY * HDIM / 4;
        const int n2 = HDIM * LIGHT / 4, n3 = HDIM * HEAVY / 4;
        const int wblocks = (n0 + n1 + n2 + n3 + 255) / 256;
        prologue_kernel<<<N_TOK / 8 + wblocks, 256>>>(
            x, router_w, router_b, probs, xh,
            light_w1, lw1h, n0, heavy_w1, hw1h, n1,
            light_w2, lw2h, n2, heavy_w2, hw2h, n3);
    }

    // merged fc1: cols [0,9) -> light (hl), cols [9,45) -> heavy (hh)
    {
        dim3 grid(LIGHT / 128 + HEAVY / 128, N_TOK / 128);
        gemm_f16_kernel<0, __half><<<grid, 128, SMEM_BYTES>>>(
            xh, lw1h, HDIM, nullptr, hw1h, HDIM, light_b1, heavy_b1,
            hl, hh, probs, LIGHT / 128);
    }
    // fc2 (dual segment): out = hl@lw2 + hh@hw2 + p0*b_l + p1*b_h
    {
        dim3 grid(HDIM / 128, N_TOK / 128);
        gemm_f16_kernel<1, float><<<grid, 128, SMEM_BYTES>>>(
            hl, lw2h, LIGHT, hh, hw2h, HEAVY, light_b2, heavy_b2,
            out, nullptr, probs, 0);
    }
}

// round 16
// speedup vs baseline: 1.2757x; 1.0021x over previous
#include <cuda_runtime.h>
#include <cuda_fp16.h>
#include <math.h>
#include <stdint.h>

// ---------------- problem constants ----------------
#define N_TOK 32768
#define HDIM  1152
#define LIGHT 1152
#define HEAVY 4608

// ---------------- static scratch (fp16 operands) ----------------
__device__ __half g_hl [(size_t)N_TOK * LIGHT];   // p0 * gelu(fc1_light)
__device__ __half g_hh [(size_t)N_TOK * HEAVY];   // p1 * gelu(fc1_heavy)
__device__ __half g_xh [(size_t)N_TOK * HDIM];
__device__ __half g_lw1h[(size_t)LIGHT * HDIM];
__device__ __half g_hw1h[(size_t)HEAVY * HDIM];
__device__ __half g_lw2h[(size_t)HDIM * LIGHT];
__device__ __half g_hw2h[(size_t)HDIM * HEAVY];
__device__ float  g_probs[2 * N_TOK];

__device__ __forceinline__ uint32_t smem_u32(const void* p) {
    uint32_t a;
    asm("{ .reg .u64 t; cvta.to.shared.u64 t, %1; cvt.u32.u64 %0, t; }" : "=r"(a) : "l"(p));
    return a;
}
__device__ __forceinline__ void cp_async16(uint32_t s, const void* g) {
    size_t gp = __cvta_generic_to_global(g);
    asm volatile("cp.async.cg.shared.global [%0], [%1], 16;" :: "r"(s), "l"(gp) : "memory");
}
#define CP_COMMIT() asm volatile("cp.async.commit_group;" ::: "memory")
#define CP_WAIT1()  asm volatile("cp.async.wait_group 1;" ::: "memory")
#define CP_WAIT0()  asm volatile("cp.async.wait_group 0;" ::: "memory")

__device__ __forceinline__ void ldmatrix_x4(uint32_t& r0, uint32_t& r1,
                                            uint32_t& r2, uint32_t& r3, uint32_t addr) {
    asm volatile("ldmatrix.sync.aligned.m8n8.x4.shared.b16 {%0,%1,%2,%3}, [%4];"
                 : "=r"(r0), "=r"(r1), "=r"(r2), "=r"(r3) : "r"(addr));
}
__device__ __forceinline__ void mma_f16(float* d, const uint32_t* a, const uint32_t* b) {
    asm volatile(
        "mma.sync.aligned.m16n8k16.row.col.f32.f16.f16.f32 "
        "{%0,%1,%2,%3}, {%4,%5,%6,%7}, {%8,%9}, {%0,%1,%2,%3};"
        : "+f"(d[0]), "+f"(d[1]), "+f"(d[2]), "+f"(d[3])
        : "r"(a[0]), "r"(a[1]), "r"(a[2]), "r"(a[3]), "r"(b[0]), "r"(b[1]));
}

// fast GELU: tanh form with HW tanh.approx.f32 (sm_75+)
__device__ __forceinline__ float gelu_fast(float v) {
    float u = 0.7978845608028654f * fmaf(0.044715f * v, v * v, v);
    float t;
    asm("tanh.approx.f32 %0, %1;" : "=f"(t) : "f"(u));
    return 0.5f * v * (1.0f + t);
}

// -------------------- merged prologue: router + fc1 weight conversions ----
// blocks [0, N_TOK/8): one warp per token -> probs + xh (float4 vectorized)
// blocks >= N_TOK/8:   fp32 -> fp16 conversion of w1 weights only
__global__ void prologue_kernel(const float* __restrict__ x,
                                const float* __restrict__ rw,
                                const float* __restrict__ rb,
                                float* __restrict__ probs,
                                __half* __restrict__ xh,
                                const float* __restrict__ s0, __half* __restrict__ d0, int n0,
                                const float* __restrict__ s1, __half* __restrict__ d1, int n1) {
    const int ROUTER_BLOCKS = N_TOK / 8;
    if ((int)blockIdx.x >= ROUTER_BLOCKS) {
        int i = ((int)blockIdx.x - ROUTER_BLOCKS) * 256 + threadIdx.x;
        const float* s; __half* d;
        if (i < n0) { s = s0; d = d0; }
        else if ((i -= n0) < n1) { s = s1; d = d1; }
        else return;
        float4 v = ((const float4*)s)[i];
        ((__half2*)d)[2 * i]     = __floats2half2_rn(v.x, v.y);
        ((__half2*)d)[2 * i + 1] = __floats2half2_rn(v.z, v.w);
        return;
    }
    int warp = (blockIdx.x * blockDim.x + threadIdx.x) >> 5;
    int lane = threadIdx.x & 31;
    const float* xp = x + (size_t)warp * HDIM;
    __half* xo = xh + (size_t)warp * HDIM;
    float a0 = 0.f, a1 = 0.f;
    #pragma unroll
    for (int it = 0; it < HDIM / 128; it++) {
        int h = it * 128 + lane * 4;
        float4 v  = *(const float4*)(xp + h);
        float4 w0 = *(const float4*)(rw + h);
        float4 w1 = *(const float4*)(rw + HDIM + h);
        ((__half2*)xo)[h / 2]     = __floats2half2_rn(v.x, v.y);
        ((__half2*)xo)[h / 2 + 1] = __floats2half2_rn(v.z, v.w);
        a0 = fmaf(v.x, w0.x, fmaf(v.y, w0.y, fmaf(v.z, w0.z, fmaf(v.w, w0.w, a0))));
        a1 = fmaf(v.x, w1.x, fmaf(v.y, w1.y, fmaf(v.z, w1.z, fmaf(v.w, w1.w, a1))));
    }
    #pragma unroll
    for (int off = 16; off; off >>= 1) {
        a0 += __shfl_xor_sync(0xffffffffu, a0, off);
        a1 += __shfl_xor_sync(0xffffffffu, a1, off);
    }
    if (lane == 0) {
        a0 += rb[0];
        a1 += rb[1];
        float m = fmaxf(a0, a1);
        float e0 = __expf(a0 - m), e1 = __expf(a1 - m);
        float inv = 1.0f / (e0 + e1);
        probs[2 * warp]     = e0 * inv;
        probs[2 * warp + 1] = e1 * inv;
    }
}

// -------------------- fp16 mma GEMM --------------------
// CTA 128x128, 128 threads, 4 warps (2x2), warp tile 64x64, BK=64,
// 3-stage cp.async, 96KB smem, 2 CTA/SM. Persistent global pointers.
// Deferred-tail pipelining + co-resident CTA phase-stagger (~1100 cyc).
// MODE 0 (merged fc1): blockIdx.y >= GEMM rows -> fc2-weight conversion blocks;
//        else blockIdx.x < ncol_light -> light expert, else heavy.
//        C[fp16] = probs[n,expert] * gelu(acc + bias[m]).
// MODE 1 (fc2): C[fp32] = acc(seg0) + acc(seg1) + p0*b0[m] + p1*b1[m].
#define STAGE_B 32768u
#define SMEM_BYTES (3 * 32768)
#define GEMM_Y (N_TOK / 128)
#define CONV_Y 32

template <int MODE, typename OutT>
__global__ void __launch_bounds__(128, 2) gemm_f16_kernel(
    const __half* __restrict__ A0, const __half* __restrict__ W0, int K0,
    const __half* __restrict__ A1, const __half* __restrict__ W1, int K1,
    const float* __restrict__ b0v, const float* __restrict__ b1v,
    OutT* __restrict__ C, OutT* __restrict__ C2,
    const float* __restrict__ probs, int ncol_light,
    const float* __restrict__ cs0, __half* __restrict__ cd0, int cn0,
    const float* __restrict__ cs1, __half* __restrict__ cd1, int cn1)
{
    // ---- MODE 0 conversion blocks (extra y-slices): convert fc2 weights
    if (MODE == 0 && (int)blockIdx.y >= GEMM_Y) {
        const int nthreads = CONV_Y * gridDim.x * 128;
        int idx = ((int)blockIdx.y - GEMM_Y) * gridDim.x * 128
                  + (int)blockIdx.x * 128 + (int)threadIdx.x;
        for (int i = idx; i < cn0 + cn1; i += nthreads) {
            const float* s; __half* d; int k = i;
            if (k < cn0) { s = cs0; d = cd0; }
            else { k -= cn0; s = cs1; d = cd1; }
            float4 v = ((const float4*)s)[k];
            ((__half2*)d)[2 * k]     = __floats2half2_rn(v.x, v.y);
            ((__half2*)d)[2 * k + 1] = __floats2half2_rn(v.z, v.w);
        }
        return;
    }

    extern __shared__ char smc[];
    const uint32_t sbase = smem_u32(smc);
    const int tid  = threadIdx.x;
    const int wid  = tid >> 5, lane = tid & 31;
    const int wr   = wid >> 1;      // 0..1 : 64-row group
    const int wn   = wid & 1;       // 0..1 : 64-col group
    const int g    = lane >> 2;     // 0..7
    const int c    = lane & 3;      // 0..3
    const int row0 = blockIdx.y * 128;

    // ---- phase-stagger: antiphase the two co-resident CTAs per SM.
    {
        const int bid = (int)(blockIdx.y * gridDim.x + blockIdx.x);
        if ((bid / 148) & 1) {
            unsigned long long t0 = clock64();
            while (clock64() - t0 < 1100ull) {}
        }
    }

    // ---- MODE 0: select expert by column-tile index
    const __half* Wsel = W0;
    const float*  bsel = b0v;
    OutT*         Csel = C;
    int           Nfeat, expert, colt;
    if (MODE == 0) {
        if ((int)blockIdx.x < ncol_light) {
            colt = blockIdx.x;              Nfeat = LIGHT; expert = 0;
        } else {
            colt = blockIdx.x - ncol_light; Nfeat = HEAVY; expert = 1;
            Wsel = W1; bsel = b1v; Csel = C2;
        }
    } else {
        colt = blockIdx.x; Nfeat = HDIM; expert = 0;
    }
    const int col0 = colt * 128;

    // ---- cp.async smem destination
    const int lrow = tid >> 3;      // 0..15
    const int ls   = tid & 7;       // 16B unit
    const uint32_t offR = (uint32_t)(lrow * 128 + ((ls ^ (lrow & 7)) * 16));

    // ---- persistent global source pointers
    const __half* pa = A0 + (size_t)(row0 + lrow) * K0 + ls * 8;
    const __half* pw = Wsel + (size_t)(col0 + lrow) * K0 + ls * 8;
    size_t rs = (size_t)16 * K0;

    // ---- ldmatrix lane components
    const int arow = wr * 64 + (lane & 15);
    const int asel = lane >> 4;
    const int nrow = wn * 64 + (lane & 7) + ((lane >> 4) << 3);
    const int bsel2 = (lane >> 3) & 1;

    float acc[4][8][4];
    #pragma unroll
    for (int i = 0; i < 4; i++)
        #pragma unroll
        for (int j = 0; j < 8; j++)
            #pragma unroll
            for (int q = 0; q < 4; q++) acc[i][j][q] = 0.f;

    const int KT0 = K0 >> 6;
    const int KT  = KT0 + ((MODE == 1) ? (K1 >> 6) : 0);

    int issued = 0;
    uint32_t so = 0;
    auto issue_next = [&]() {
        if (MODE == 1 && issued == KT0) {
            pa = A1 + (size_t)(row0 + lrow) * K1 + ls * 8;
            pw = W1 + (size_t)(col0 + lrow) * K1 + ls * 8;
            rs = (size_t)16 * K1;
        }
        #pragma unroll
        for (int i = 0; i < 8; i++) {
            cp_async16(sbase + so + offR + (uint32_t)i * 2048u,          pa + (size_t)i * rs);
            cp_async16(sbase + so + 16384u + offR + (uint32_t)i * 2048u, pw + (size_t)i * rs);
        }
        pa += 64; pw += 64;
        issued++;
        so += STAGE_B; if (so == 3 * STAGE_B) so = 0;
    };

    // fragment buffers (live across the chunk boundary for the deferred tail)
    uint32_t af[2][4][4], bf[2][4][4];

    auto ldA = [&](uint32_t as, int ks, uint32_t dst[4][4]) {
        const uint32_t p = (uint32_t)((((ks * 2 + asel) ^ (arow & 7)) * 16));
        const uint32_t base = as + (uint32_t)(arow * 128) + p;
        #pragma unroll
        for (int i = 0; i < 4; i++)
            ldmatrix_x4(dst[i][0], dst[i][1], dst[i][2], dst[i][3], base + (uint32_t)(i * 2048));
    };
    auto ldB = [&](uint32_t ws, int ks, uint32_t dst[4][4]) {
        const uint32_t p = (uint32_t)((((ks * 2 + bsel2) ^ (nrow & 7)) * 16));
        const uint32_t base = ws + (uint32_t)(nrow * 128) + p;
        #pragma unroll
        for (int j2 = 0; j2 < 4; j2++)
            ldmatrix_x4(dst[j2][0], dst[j2][1], dst[j2][2], dst[j2][3], base + (uint32_t)(j2 * 2048));
    };
    auto mma_block = [&](int buf) {
        #pragma unroll
        for (int i = 0; i < 4; i++)
            #pragma unroll
            for (int j = 0; j < 8; j++)
                mma_f16(acc[i][j], af[buf][i], &bf[buf][j >> 1][(j & 1) * 2]);
    };
    // k-steps 0..2 (+frag prefetch); leaves step-3 fragments in buf 1
    auto compute_head = [&](uint32_t co) {
        const uint32_t as = sbase + co;
        const uint32_t ws = as + 16384u;
        ldB(ws, 0, bf[0]);
        ldA(as, 0, af[0]);
        #pragma unroll
        for (int ks = 0; ks < 3; ks++) {
            const int cur = ks & 1;
            ldB(ws, ks + 1, bf[cur ^ 1]);
            ldA(as, ks + 1, af[cur ^ 1]);
            mma_block(cur);
        }
    };

    issue_next(); CP_COMMIT();
    issue_next(); CP_COMMIT();
    uint32_t co = 0;

    // prologue iteration (kt = 0)
    CP_WAIT1();
    __syncthreads();
    if (KT > 2) issue_next();
    CP_COMMIT();
    compute_head(co);
    co += STAGE_B; if (co == 3 * STAGE_B) co = 0;

    for (int kt = 1; kt < KT; kt++) {
        mma_block(1);               // deferred step-3 mma of previous chunk
        CP_WAIT1();
        __syncthreads();
        if (kt + 2 < KT) issue_next();
        CP_COMMIT();
        compute_head(co);
        co += STAGE_B; if (co == 3 * STAGE_B) co = 0;
    }
    mma_block(1);                   // final deferred tail
    CP_WAIT0();

    // -------- epilogue --------
    #pragma unroll
    for (int i = 0; i < 4; i++) {
        const int rowA = row0 + wr * 64 + i * 16 + g;
        float p0a, p1a, p0b, p1b;
        if (MODE == 0) {
            p0a = probs[2 * rowA + expert];
            p0b = probs[2 * (rowA + 8) + expert];
            p1a = p1b = 0.f;
        } else {
            p0a = probs[2 * rowA];       p1a = probs[2 * rowA + 1];
            p0b = probs[2 * (rowA + 8)]; p1b = probs[2 * (rowA + 8) + 1];
        }
        #pragma unroll
        for (int j = 0; j < 8; j++) {
            const int col = col0 + wn * 64 + j * 8 + c * 2;
            OutT* out0 = Csel + (size_t)rowA * Nfeat + col;
            OutT* out1 = Csel + (size_t)(rowA + 8) * Nfeat + col;
            if (MODE == 0) {
                const float b0 = bsel[col], b1 = bsel[col + 1];
                *(__half2*)out0 = __floats2half2_rn(p0a * gelu_fast(acc[i][j][0] + b0),
                                                    p0a * gelu_fast(acc[i][j][1] + b1));
                *(__half2*)out1 = __floats2half2_rn(p0b * gelu_fast(acc[i][j][2] + b0),
                                                    p0b * gelu_fast(acc[i][j][3] + b1));
            } else {
                const float bl0 = b0v[col], bl1 = b0v[col + 1];
                const float bh0 = b1v[col], bh1 = b1v[col + 1];
                out0[0] = acc[i][j][0] + p0a * bl0 + p1a * bh0;
                out0[1] = acc[i][j][1] + p0a * bl1 + p1a * bh1;
                out1[0] = acc[i][j][2] + p0b * bl0 + p1b * bh0;
                out1[1] = acc[i][j][3] + p0b * bl1 + p1b * bh1;
            }
        }
    }
}

// -------------------- launch --------------------
extern "C" void kernel_launch(void* const* d_in, const int* in_sizes, int n_in,
                              void* d_out, int out_size) {
    const float* x        = (const float*)d_in[0];
    const float* router_w = (const float*)d_in[1];
    const float* router_b = (const float*)d_in[2];
    const float* light_w1 = (const float*)d_in[3];
    const float* light_b1 = (const float*)d_in[4];
    const float* light_w2 = (const float*)d_in[5];
    const float* light_b2 = (const float*)d_in[6];
    const float* heavy_w1 = (const float*)d_in[7];
    const float* heavy_b1 = (const float*)d_in[8];
    const float* heavy_w2 = (const float*)d_in[9];
    const float* heavy_b2 = (const float*)d_in[10];
    float* out = (float*)d_out;

    __half *hl, *hh, *xh, *lw1h, *hw1h, *lw2h, *hw2h;
    float* probs;
    cudaGetSymbolAddress((void**)&hl, g_hl);
    cudaGetSymbolAddress((void**)&hh, g_hh);
    cudaGetSymbolAddress((void**)&xh, g_xh);
    cudaGetSymbolAddress((void**)&lw1h, g_lw1h);
    cudaGetSymbolAddress((void**)&hw1h, g_hw1h);
    cudaGetSymbolAddress((void**)&lw2h, g_lw2h);
    cudaGetSymbolAddress((void**)&hw2h, g_hw2h);
    cudaGetSymbolAddress((void**)&probs, g_probs);

    static bool attr_done = false;
    if (!attr_done) {
        cudaFuncSetAttribute((const void*)gemm_f16_kernel<0, __half>,
                             cudaFuncAttributeMaxDynamicSharedMemorySize, SMEM_BYTES);
        cudaFuncSetAttribute((const void*)gemm_f16_kernel<1, float>,
                             cudaFuncAttributeMaxDynamicSharedMemorySize, SMEM_BYTES);
        attr_done = true;
    }

    // prologue: router (vectorized) + w1 conversions only
    {
        const int n0 = LIGHT * HDIM / 4, n1 = HEAVY * HDIM / 4;
        const int wblocks = (n0 + n1 + 255) / 256;
        prologue_kernel<<<N_TOK / 8 + wblocks, 256>>>(
            x, router_w, router_b, probs, xh,
            light_w1, lw1h, n0, heavy_w1, hw1h, n1);
    }

    // merged fc1: cols [0,9) -> light (hl), cols [9,45) -> heavy (hh);
    // extra y-slices convert fc2 weights (lw2/hw2) under fc1's idle DRAM.
    {
        dim3 grid(LIGHT / 128 + HEAVY / 128, GEMM_Y + CONV_Y);
        gemm_f16_kernel<0, __half><<<grid, 128, SMEM_BYTES>>>(
            xh, lw1h, HDIM, nullptr, hw1h, HDIM, light_b1, heavy_b1,
            hl, hh, probs, LIGHT / 128,
            light_w2, lw2h, HDIM * LIGHT / 4, heavy_w2, hw2h, HDIM * HEAVY / 4);
    }
    // fc2 (dual segment): out = hl@lw2 + hh@hw2 + p0*b_l + p1*b_h
    {
        dim3 grid(HDIM / 128, GEMM_Y);
        gemm_f16_kernel<1, float><<<grid, 128, SMEM_BYTES>>>(
            hl, lw2h, LIGHT, hh, hw2h, HEAVY, light_b2, heavy_b2,
            out, nullptr, probs, 0,
            nullptr, nullptr, 0, nullptr, nullptr, 0);
    }
}